// round 14
// baseline (speedup 1.0000x reference)
#include <cuda_runtime.h>
#include <cuda_fp16.h>
#include <math.h>
#include <stdint.h>

#define N_NODES 20000
#define N_EDGES 640000
#define E_TOT   660000          // + self loops
#define H1      4
#define C       128
#define HC1     (H1 * C)        // 512

// ---------------- scratch (no allocations allowed) ----------------
__device__ __half g_W1s[HC1 * C];        // stacked+scaled: [512 x 128]
__device__ __half g_W2h[C * C];
__device__ __half g_yh[N_NODES * HC1];   // per-head aggregated x (normalized), fp16
__device__ float  g_x2f[N_NODES * C];    // layer-1 output (fp32, gathered by agg2)
__device__ __half g_y2h[N_NODES * C];
__device__ float  g_p1[4 * E_TOT];       // layer-1 per-edge softmax numerators
__device__ float  g_p2[E_TOT];           // layer-2 per-edge numerators
__device__ float  g_as1[N_NODES * H1];
__device__ float  g_ad1[N_NODES * H1];
__device__ float  g_as2[N_NODES];
__device__ float  g_ad2[N_NODES];
__device__ float  g_was1[C * H1];
__device__ float  g_wad1[C * H1];
__device__ float  g_was2[C];
__device__ float  g_wad2[C];
__device__ int    g_rowptr[N_NODES + 1];
__device__ int    g_cursor[N_NODES];
__device__ int    g_cnt[N_NODES];       // zero-initialized; scan re-zeroes after use
__device__ int    g_csrc[E_TOT + 1];    // +1 pad for unconditional prefetch

__device__ __forceinline__ unsigned int smem_u32(const void* p)
{
    return (unsigned int)__cvta_generic_to_shared(p);
}
__device__ __forceinline__ unsigned long long pack_f32x2(float lo, float hi)
{
    unsigned long long r;
    asm("mov.b64 %0, {%1, %2};" : "=l"(r) : "f"(lo), "f"(hi));
    return r;
}
__device__ __forceinline__ void unpack_f32x2(float& lo, float& hi, unsigned long long v)
{
    asm("mov.b64 {%0, %1}, %2;" : "=f"(lo), "=f"(hi) : "l"(v));
}
__device__ __forceinline__ unsigned long long fma_f32x2(
    unsigned long long a, unsigned long long b, unsigned long long c)
{
    unsigned long long d;
    asm("fma.rn.f32x2 %0, %1, %2, %3;" : "=l"(d) : "l"(a), "l"(b), "l"(c));
    return d;
}

// ================= prep: wfold + fp16 converts (W1s stacked, W2) + degree count =================
__global__ __launch_bounds__(256) void prep_kernel(
    const float* __restrict__ W1, const float* __restrict__ W2,
    const float* __restrict__ as1, const float* __restrict__ ad1,
    const float* __restrict__ as2, const float* __restrict__ ad2,
    const int* __restrict__ ei,
    __half* __restrict__ W1s, __half* __restrict__ W2h,
    float* __restrict__ w_as1, float* __restrict__ w_ad1,
    float* __restrict__ w_as2, float* __restrict__ w_ad2,
    int* __restrict__ cnt, int* __restrict__ csrc)
{
    const int R1 = HC1 * C / 4;          // 16384   W1 -> W1s (transposed blocks, 0.25x)
    const int R2 = C * C / 4;            // 4096    W2 -> W2h
    int gid = blockIdx.x * blockDim.x + threadIdx.x;

    if (gid == 0) csrc[E_TOT] = 0;      // prefetch pad

    if (gid < R1) {
        int r = gid >> 5;                // row of W1s: 0..511
        int jc = (gid & 31) * 4;         // col
        int h = r >> 7, i = r & 127;
        float4 v = *(const float4*)&W1[(size_t)i * HC1 + h * C + jc];
        __half2* d2 = (__half2*)(W1s + (size_t)r * C + jc);
        d2[0] = __floats2half2_rn(0.25f * v.x, 0.25f * v.y);
        d2[1] = __floats2half2_rn(0.25f * v.z, 0.25f * v.w);
    } else if (gid < R1 + R2) {
        int m = gid - R1;
        float4 v = ((const float4*)W2)[m];
        __half2* d2 = (__half2*)(W2h + (size_t)m * 4);
        d2[0] = __floats2half2_rn(v.x, v.y);
        d2[1] = __floats2half2_rn(v.z, v.w);
    }
    if (gid < E_TOT) {
        int d = (gid < N_EDGES) ? ei[N_EDGES + gid] : (gid - N_EDGES);
        atomicAdd(&cnt[d], 1);
    }
    int w = gid >> 5, lane = gid & 31;
    if (w < 512) {
        int k = w >> 2, h = w & 3;
        float4 wv = *(const float4*)&W1[(size_t)k * HC1 + h * C + lane * 4];
        float4 av = *(const float4*)&as1[h * C + lane * 4];
        float4 dv = *(const float4*)&ad1[h * C + lane * 4];
        float ss = wv.x * av.x + wv.y * av.y + wv.z * av.z + wv.w * av.w;
        float sd = wv.x * dv.x + wv.y * dv.y + wv.z * dv.z + wv.w * dv.w;
#pragma unroll
        for (int off = 16; off > 0; off >>= 1) {
            ss += __shfl_down_sync(0xffffffff, ss, off);
            sd += __shfl_down_sync(0xffffffff, sd, off);
        }
        if (lane == 0) { w_as1[k * H1 + h] = ss; w_ad1[k * H1 + h] = sd; }
    } else if (w < 640) {
        int k = w - 512;
        float4 wv = *(const float4*)&W2[(size_t)k * C + lane * 4];
        float4 av = *(const float4*)&as2[lane * 4];
        float4 dv = *(const float4*)&ad2[lane * 4];
        float ss = wv.x * av.x + wv.y * av.y + wv.z * av.z + wv.w * av.w;
        float sd = wv.x * dv.x + wv.y * dv.y + wv.z * dv.z + wv.w * dv.w;
#pragma unroll
        for (int off = 16; off > 0; off >>= 1) {
            ss += __shfl_down_sync(0xffffffff, ss, off);
            sd += __shfl_down_sync(0xffffffff, sd, off);
        }
        if (lane == 0) { w_as2[k] = ss; w_ad2[k] = sd; }
    }
}

// ================= coalesced smem-staged scan (1 block); zeroes cnt afterward =================
#define SCAN_ELEMS 20480   // 1024 * 20
__global__ __launch_bounds__(1024) void scan_kernel(
    int* __restrict__ cnt, int* __restrict__ rowptr, int* __restrict__ cursor)
{
    extern __shared__ int sm[];
    __shared__ int part[1024];
    const int t = threadIdx.x;
    const int CHUNK = 20;

    for (int i = t; i < SCAN_ELEMS; i += 1024)
        sm[i] = (i < N_NODES) ? cnt[i] : 0;
    __syncthreads();

    int base = t * CHUNK;
    int s = 0;
#pragma unroll
    for (int k = 0; k < CHUNK; k++) s += sm[base + k];
    part[t] = s;
    __syncthreads();
    for (int off = 1; off < 1024; off <<= 1) {
        int v = (t >= off) ? part[t - off] : 0;
        __syncthreads();
        part[t] += v;
        __syncthreads();
    }
    int run = part[t] - s;
#pragma unroll
    for (int k = 0; k < CHUNK; k++) {
        int c = sm[base + k];
        sm[base + k] = run;
        run += c;
    }
    __syncthreads();
    for (int i = t; i < N_NODES; i += 1024) {
        int v = sm[i];
        rowptr[i] = v;
        cursor[i] = v;
        cnt[i] = 0;
    }
    if (t == 1023) rowptr[N_NODES] = part[1023];
}

// ================= fused: CSR scatter + layer-1 logits =================
#define SC_BLOCKS  ((E_TOT + 255) / 256)
#define AL_BLOCKS  ((N_NODES * 32 + 255) / 256)
__global__ __launch_bounds__(256) void fused_sa_kernel(
    const int* __restrict__ ei, int* __restrict__ cursor, int* __restrict__ csrc,
    const float* __restrict__ x, const float* __restrict__ w_as1,
    const float* __restrict__ w_ad1, float* __restrict__ as_o,
    float* __restrict__ ad_o)
{
    int bid = blockIdx.x;
    if (bid < SC_BLOCKS) {
        int i = bid * 256 + threadIdx.x;
        if (i < E_TOT) {
            int s, d;
            if (i < N_EDGES) { s = ei[i]; d = ei[N_EDGES + i]; }
            else { s = d = i - N_EDGES; }
            int pos = atomicAdd(&cursor[d], 1);
            csrc[pos] = s;
        }
        return;
    }
    bid -= SC_BLOCKS;
    {
        __shared__ float sw_s[C * H1], sw_d[C * H1];
        for (int i = threadIdx.x; i < C * H1; i += 256) {
            sw_s[i] = w_as1[i]; sw_d[i] = w_ad1[i];
        }
        __syncthreads();
        int n = (bid * 256 + threadIdx.x) >> 5;
        int lane = threadIdx.x & 31;
        if (n >= N_NODES) return;
        float4 xv = *(const float4*)&x[(size_t)n * C + lane * 4];
        float xs[4] = {xv.x, xv.y, xv.z, xv.w};
        float ps[4] = {0, 0, 0, 0}, pd[4] = {0, 0, 0, 0};
#pragma unroll
        for (int j = 0; j < 4; j++) {
            int k = lane * 4 + j;
#pragma unroll
            for (int h = 0; h < 4; h++) {
                ps[h] += xs[j] * sw_s[k * 4 + h];
                pd[h] += xs[j] * sw_d[k * 4 + h];
            }
        }
#pragma unroll
        for (int off = 16; off > 0; off >>= 1) {
#pragma unroll
            for (int h = 0; h < 4; h++) {
                ps[h] += __shfl_down_sync(0xffffffff, ps[h], off);
                pd[h] += __shfl_down_sync(0xffffffff, pd[h], off);
            }
        }
        if (lane == 0) {
            *(float4*)&as_o[n * 4] = make_float4(ps[0], ps[1], ps[2], ps[3]);
            *(float4*)&ad_o[n * 4] = make_float4(pd[0], pd[1], pd[2], pd[3]);
        }
    }
}

// ================= layer-1 aggregation: two-phase, fp32 x gather, FFMA2, no converts =================
__global__ __launch_bounds__(256) void agg1_kernel(
    const int* __restrict__ rowptr, const int* __restrict__ csrc,
    const float* __restrict__ as_v, const float* __restrict__ ad_v,
    const float* __restrict__ x, float* __restrict__ p1,
    __half* __restrict__ yh)
{
    int n = (blockIdx.x * 256 + threadIdx.x) >> 5;
    int lane = threadIdx.x & 31;
    if (n >= N_NODES) return;
    int start = rowptr[n], end = rowptr[n + 1];
    float4 adn = *(const float4*)&ad_v[n * 4];

    // ---- phase 1: per-edge softmax numerators (lanes parallel over edges) ----
    float d0 = 0.f, d1 = 0.f, d2 = 0.f, d3 = 0.f;
    for (int e = start + lane; e < end; e += 32) {
        int s = csrc[e];
        float4 lg = *(const float4*)&as_v[s * 4];
        float l0 = lg.x + adn.x; l0 = fmaxf(l0, 0.2f * l0);
        float l1 = lg.y + adn.y; l1 = fmaxf(l1, 0.2f * l1);
        float l2 = lg.z + adn.z; l2 = fmaxf(l2, 0.2f * l2);
        float l3 = lg.w + adn.w; l3 = fmaxf(l3, 0.2f * l3);
        float p0 = __expf(l0), pp1 = __expf(l1), p2 = __expf(l2), p3 = __expf(l3);
        *(float4*)&p1[(size_t)e * 4] = make_float4(p0, pp1, p2, p3);
        d0 += p0; d1 += pp1; d2 += p2; d3 += p3;
    }
#pragma unroll
    for (int off = 16; off > 0; off >>= 1) {
        d0 += __shfl_xor_sync(0xffffffff, d0, off);
        d1 += __shfl_xor_sync(0xffffffff, d1, off);
        d2 += __shfl_xor_sync(0xffffffff, d2, off);
        d3 += __shfl_xor_sync(0xffffffff, d3, off);
    }
    __syncwarp();                         // order p1 stores before phase-2 loads

    const int grp = lane >> 4;            // 0: heads 0/1, 1: heads 2/3
    const int sub = lane & 15;
    float invP = 1.f / (grp ? d2 : d0);
    float invQ = 1.f / (grp ? d3 : d1);

    // ---- phase 2: fp32 gather + packed FFMA2 (no exp, no den, no cvt) ----
    unsigned long long aP0 = 0ull, aP1 = 0ull, aP2 = 0ull, aP3 = 0ull;
    unsigned long long aQ0 = 0ull, aQ1 = 0ull, aQ2 = 0ull, aQ3 = 0ull;

    int sA = csrc[start];                 // deg >= 1 (self loop)
    for (int e = start; e < end; e++) {
        int s = sA;
        sA = csrc[e + 1];                 // padded: always safe
        float2 pq = *(const float2*)&p1[(size_t)e * 4 + grp * 2];
        unsigned long long pP2 = pack_f32x2(pq.x, pq.x);
        unsigned long long pQ2 = pack_f32x2(pq.y, pq.y);
        const ulonglong2* xr = (const ulonglong2*)(x + (size_t)s * C + sub * 8);
        ulonglong2 q0 = xr[0];
        ulonglong2 q1 = xr[1];
        aP0 = fma_f32x2(q0.x, pP2, aP0); aP1 = fma_f32x2(q0.y, pP2, aP1);
        aP2 = fma_f32x2(q1.x, pP2, aP2); aP3 = fma_f32x2(q1.y, pP2, aP3);
        aQ0 = fma_f32x2(q0.x, pQ2, aQ0); aQ1 = fma_f32x2(q0.y, pQ2, aQ1);
        aQ2 = fma_f32x2(q1.x, pQ2, aQ2); aQ3 = fma_f32x2(q1.y, pQ2, aQ3);
    }
    float vP[8], vQ[8];
    unpack_f32x2(vP[0], vP[1], aP0); unpack_f32x2(vP[2], vP[3], aP1);
    unpack_f32x2(vP[4], vP[5], aP2); unpack_f32x2(vP[6], vP[7], aP3);
    unpack_f32x2(vQ[0], vQ[1], aQ0); unpack_f32x2(vQ[2], vQ[3], aQ1);
    unpack_f32x2(vQ[4], vQ[5], aQ2); unpack_f32x2(vQ[6], vQ[7], aQ3);
    __half hP[8], hQ[8];
#pragma unroll
    for (int j = 0; j < 8; j++) {
        hP[j] = __float2half(vP[j] * invP);
        hQ[j] = __float2half(vQ[j] * invQ);
    }
    *(uint4*)&yh[(size_t)n * HC1 + (grp * 2) * C + sub * 8]     = *(uint4*)hP;
    *(uint4*)&yh[(size_t)n * HC1 + (grp * 2 + 1) * C + sub * 8] = *(uint4*)hQ;
}

// ================= tensor-core GEMM + bias + ELU (+ optional layer-2 logits) =================
// C[M,128] = A[M,KDIM] * B[KDIM,128]; CTA 128x128, BK=64, 8 warps (4M x 2N)
template <int KDIM, bool OUT_HALF, bool DO_LOGITS>
__global__ __launch_bounds__(256) void gemm_bias_elu_kernel(
    const __half* __restrict__ A, const __half* __restrict__ B,
    const float* __restrict__ bias, void* __restrict__ Cout, int M,
    const float* __restrict__ w_s, const float* __restrict__ w_d,
    float* __restrict__ as_o, float* __restrict__ ad_o)
{
    __shared__ __half As[128][64];
    __shared__ __half Bs[64][128];
    __shared__ float sw_s[DO_LOGITS ? C : 1], sw_d[DO_LOGITS ? C : 1];
    __shared__ float redS[DO_LOGITS ? 128 : 1][2], redD[DO_LOGITS ? 128 : 1][2];

    const int tid = threadIdx.x;
    const int lane = tid & 31, wid = tid >> 5;
    const int warpM = wid >> 1, warpN = wid & 1;
    const int rowBase = blockIdx.x * 128;

    if (DO_LOGITS) {
        for (int i = tid; i < C; i += 256) { sw_s[i] = w_s[i]; sw_d[i] = w_d[i]; }
    }

    float acc[2][8][4];
#pragma unroll
    for (int mi = 0; mi < 2; mi++)
#pragma unroll
        for (int ni = 0; ni < 8; ni++)
#pragma unroll
            for (int q = 0; q < 4; q++) acc[mi][ni][q] = 0.f;

    const int arow0 = warpM * 32 + (lane & 15);
    const int brow0 = (lane & 15);
    const int hi = (lane >> 4);

    for (int kt = 0; kt < KDIM / 64; kt++) {
#pragma unroll
        for (int i = tid; i < 1024; i += 256) {
            int r = i >> 3, ch = i & 7;
            int gr = rowBase + r;
            uint4 v = make_uint4(0u, 0u, 0u, 0u);
            if (gr < M) v = *(const uint4*)&A[(size_t)gr * KDIM + kt * 64 + ch * 8];
            int sch = ch ^ (r & 7);
            *(uint4*)&As[r][sch * 8] = v;
        }
#pragma unroll
        for (int i = tid; i < 1024; i += 256) {
            int r = i >> 4, ch = i & 15;
            uint4 v = *(const uint4*)&B[(size_t)(kt * 64 + r) * C + ch * 8];
            int sch = (ch & 8) | ((ch & 7) ^ (r & 7));
            *(uint4*)&Bs[r][sch * 8] = v;
        }
        __syncthreads();

#pragma unroll
        for (int kk = 0; kk < 4; kk++) {
            unsigned int a[2][4];
#pragma unroll
            for (int mi = 0; mi < 2; mi++) {
                int r = arow0 + mi * 16;
                int ch = (kk * 2 + hi) ^ (r & 7);
                unsigned int addr = smem_u32(&As[r][ch * 8]);
                asm volatile("ldmatrix.sync.aligned.m8n8.x4.shared.b16 {%0,%1,%2,%3}, [%4];"
                    : "=r"(a[mi][0]), "=r"(a[mi][1]), "=r"(a[mi][2]), "=r"(a[mi][3])
                    : "r"(addr));
            }
            unsigned int b[8][2];
#pragma unroll
            for (int np = 0; np < 4; np++) {
                int r = kk * 16 + brow0;
                int chL = warpN * 8 + np * 2 + hi;
                int ch = (chL & 8) | ((chL & 7) ^ (r & 7));
                unsigned int addr = smem_u32(&Bs[r][ch * 8]);
                unsigned int r0, r1, r2, r3;
                asm volatile("ldmatrix.sync.aligned.m8n8.x4.trans.shared.b16 {%0,%1,%2,%3}, [%4];"
                    : "=r"(r0), "=r"(r1), "=r"(r2), "=r"(r3) : "r"(addr));
                b[np * 2][0] = r0;     b[np * 2][1] = r1;
                b[np * 2 + 1][0] = r2; b[np * 2 + 1][1] = r3;
            }
#pragma unroll
            for (int mi = 0; mi < 2; mi++)
#pragma unroll
                for (int ni = 0; ni < 8; ni++)
                    asm volatile(
                        "mma.sync.aligned.m16n8k16.row.col.f32.f16.f16.f32 "
                        "{%0,%1,%2,%3},{%4,%5,%6,%7},{%8,%9},{%0,%1,%2,%3};"
                        : "+f"(acc[mi][ni][0]), "+f"(acc[mi][ni][1]),
                          "+f"(acc[mi][ni][2]), "+f"(acc[mi][ni][3])
                        : "r"(a[mi][0]), "r"(a[mi][1]), "r"(a[mi][2]), "r"(a[mi][3]),
                          "r"(b[ni][0]), "r"(b[ni][1]));
        }
        __syncthreads();
    }

    // ---- epilogue: bias + ELU (+ logits) ----
    float psum[2][2], pdum[2][2];
    if (DO_LOGITS) {
        psum[0][0] = psum[0][1] = psum[1][0] = psum[1][1] = 0.f;
        pdum[0][0] = pdum[0][1] = pdum[1][0] = pdum[1][1] = 0.f;
    }
#pragma unroll
    for (int mi = 0; mi < 2; mi++) {
        int r0 = rowBase + warpM * 32 + mi * 16 + (lane >> 2);
#pragma unroll
        for (int ni = 0; ni < 8; ni++) {
            int col = warpN * 64 + ni * 8 + (lane & 3) * 2;
            float b0 = bias[col], b1v = bias[col + 1];
            float v0 = acc[mi][ni][0] + b0;  v0 = v0 > 0.f ? v0 : expm1f(v0);
            float v1 = acc[mi][ni][1] + b1v; v1 = v1 > 0.f ? v1 : expm1f(v1);
            float v2 = acc[mi][ni][2] + b0;  v2 = v2 > 0.f ? v2 : expm1f(v2);
            float v3 = acc[mi][ni][3] + b1v; v3 = v3 > 0.f ? v3 : expm1f(v3);
            if (DO_LOGITS) {
                psum[mi][0] += v0 * sw_s[col] + v1 * sw_s[col + 1];
                psum[mi][1] += v2 * sw_s[col] + v3 * sw_s[col + 1];
                pdum[mi][0] += v0 * sw_d[col] + v1 * sw_d[col + 1];
                pdum[mi][1] += v2 * sw_d[col] + v3 * sw_d[col + 1];
            }
            if (OUT_HALF) {
                __half* Ch = (__half*)Cout;
                if (r0 < M)
                    *(__half2*)&Ch[(size_t)r0 * C + col] = __floats2half2_rn(v0, v1);
                if (r0 + 8 < M)
                    *(__half2*)&Ch[(size_t)(r0 + 8) * C + col] = __floats2half2_rn(v2, v3);
            } else {
                float* Cf = (float*)Cout;
                if (r0 < M)
                    *(float2*)&Cf[(size_t)r0 * C + col] = make_float2(v0, v1);
                if (r0 + 8 < M)
                    *(float2*)&Cf[(size_t)(r0 + 8) * C + col] = make_float2(v2, v3);
            }
        }
    }
    if (DO_LOGITS) {
#pragma unroll
        for (int mi = 0; mi < 2; mi++)
#pragma unroll
            for (int rh = 0; rh < 2; rh++) {
                float s = psum[mi][rh], d = pdum[mi][rh];
                s += __shfl_xor_sync(0xffffffff, s, 1);
                s += __shfl_xor_sync(0xffffffff, s, 2);
                d += __shfl_xor_sync(0xffffffff, d, 1);
                d += __shfl_xor_sync(0xffffffff, d, 2);
                if ((lane & 3) == 0) {
                    int lr = warpM * 32 + mi * 16 + rh * 8 + (lane >> 2);
                    redS[lr][warpN] = s;
                    redD[lr][warpN] = d;
                }
            }
        __syncthreads();
        if (tid < 128) {
            int rg = rowBase + tid;
            if (rg < M) {
                as_o[rg] = redS[tid][0] + redS[tid][1];
                ad_o[rg] = redD[tid][0] + redD[tid][1];
            }
        }
    }
}

// ================= layer-2 aggregation: two-phase, fp32 x2 gather, FFMA2 =================
__global__ __launch_bounds__(256) void agg2_kernel(
    const int* __restrict__ rowptr, const int* __restrict__ csrc,
    const float* __restrict__ as_v, const float* __restrict__ ad_v,
    const float* __restrict__ x2f, float* __restrict__ p2,
    __half* __restrict__ y2h)
{
    int n = (blockIdx.x * 256 + threadIdx.x) >> 5;
    int lane = threadIdx.x & 31;
    if (n >= N_NODES) return;
    int start = rowptr[n], end = rowptr[n + 1];
    float adn = ad_v[n];

    // ---- phase 1: per-edge numerators ----
    float den = 0.f;
    for (int e = start + lane; e < end; e += 32) {
        int s = csrc[e];
        float l = as_v[s] + adn;
        l = fmaxf(l, 0.2f * l);
        float p = __expf(l);
        p2[e] = p;
        den += p;
    }
#pragma unroll
    for (int off = 16; off > 0; off >>= 1)
        den += __shfl_xor_sync(0xffffffff, den, off);
    __syncwarp();
    float inv = 1.f / den;

    // ---- phase 2: fp32 gather + packed FFMA2 ----
    unsigned long long a0 = 0ull, a1 = 0ull;
    int sA = csrc[start];
    for (int e = start; e < end; e++) {
        int s = sA;
        sA = csrc[e + 1];
        float p = p2[e];
        unsigned long long pp = pack_f32x2(p, p);
        ulonglong2 q = *(const ulonglong2*)(x2f + (size_t)s * C + lane * 4);
        a0 = fma_f32x2(q.x, pp, a0);
        a1 = fma_f32x2(q.y, pp, a1);
    }
    float v0, v1, v2, v3;
    unpack_f32x2(v0, v1, a0);
    unpack_f32x2(v2, v3, a1);
    __half2 o0 = __floats2half2_rn(v0 * inv, v1 * inv);
    __half2 o1 = __floats2half2_rn(v2 * inv, v3 * inv);
    uint2 o; o.x = *(unsigned int*)&o0; o.y = *(unsigned int*)&o1;
    *(uint2*)&y2h[(size_t)n * C + lane * 4] = o;
}

// ---------------- launch ----------------
extern "C" void kernel_launch(void* const* d_in, const int* in_sizes, int n_in,
                              void* d_out, int out_size)
{
    const float* x      = (const float*)d_in[0];
    const float* W1     = (const float*)d_in[1];
    const float* a_src1 = (const float*)d_in[2];
    const float* a_dst1 = (const float*)d_in[3];
    const float* b1     = (const float*)d_in[4];
    const float* W2     = (const float*)d_in[5];
    const float* a_src2 = (const float*)d_in[6];
    const float* a_dst2 = (const float*)d_in[7];
    const float* b2     = (const float*)d_in[8];
    const int*   ei     = (const int*)d_in[9];
    float* out = (float*)d_out;

    __half *W1s, *W2h, *yh, *y2h;
    float *x2f, *p1, *p2, *as1, *ad1, *as2, *ad2, *was1, *wad1, *was2, *wad2;
    int *rowptr, *cursor, *cnt, *csrc;
    cudaGetSymbolAddress((void**)&W1s,    g_W1s);
    cudaGetSymbolAddress((void**)&W2h,    g_W2h);
    cudaGetSymbolAddress((void**)&yh,     g_yh);
    cudaGetSymbolAddress((void**)&x2f,    g_x2f);
    cudaGetSymbolAddress((void**)&y2h,    g_y2h);
    cudaGetSymbolAddress((void**)&p1,     g_p1);
    cudaGetSymbolAddress((void**)&p2,     g_p2);
    cudaGetSymbolAddress((void**)&as1,    g_as1);
    cudaGetSymbolAddress((void**)&ad1,    g_ad1);
    cudaGetSymbolAddress((void**)&as2,    g_as2);
    cudaGetSymbolAddress((void**)&ad2,    g_ad2);
    cudaGetSymbolAddress((void**)&was1,   g_was1);
    cudaGetSymbolAddress((void**)&wad1,   g_wad1);
    cudaGetSymbolAddress((void**)&was2,   g_was2);
    cudaGetSymbolAddress((void**)&wad2,   g_wad2);
    cudaGetSymbolAddress((void**)&rowptr, g_rowptr);
    cudaGetSymbolAddress((void**)&cursor, g_cursor);
    cudaGetSymbolAddress((void**)&cnt,    g_cnt);
    cudaGetSymbolAddress((void**)&csrc,   g_csrc);

    const int TPB = 256;
    int prep_blocks = (E_TOT + TPB - 1) / TPB;

    cudaFuncSetAttribute(scan_kernel, cudaFuncAttributeMaxDynamicSharedMemorySize,
                         SCAN_ELEMS * (int)sizeof(int));

    const int GEMM_GRID = (N_NODES + 127) / 128;   // 157
    const int WARP_GRID = (N_NODES * 32 + TPB - 1) / TPB;

    // 1) prep: wfold + weight converts + count (+ csrc pad)
    prep_kernel<<<prep_blocks, TPB>>>(W1, W2, a_src1, a_dst1, a_src2, a_dst2, ei,
                                      W1s, W2h, was1, wad1, was2, wad2, cnt, csrc);
    // 2) scan
    scan_kernel<<<1, 1024, SCAN_ELEMS * sizeof(int)>>>(cnt, rowptr, cursor);
    // 3) fused: scatter + alphas1
    fused_sa_kernel<<<SC_BLOCKS + AL_BLOCKS, TPB>>>(
        ei, cursor, csrc, x, was1, wad1, as1, ad1);
    // 4) layer-1 aggregation (two-phase, fp32 gather, FFMA2) -> yh
    agg1_kernel<<<WARP_GRID, TPB>>>(rowptr, csrc, as1, ad1, x, p1, yh);
    // 5) gemm-mid: x2 = ELU(yh * W1s + b1) fp32; epilogue computes layer-2 logits
    gemm_bias_elu_kernel<HC1, false, true><<<GEMM_GRID, TPB>>>(
        yh, W1s, b1, x2f, N_NODES, was2, wad2, as2, ad2);
    // 6) layer-2 aggregation (two-phase, fp32 gather, FFMA2) -> y2
    agg2_kernel<<<WARP_GRID, TPB>>>(rowptr, csrc, as2, ad2, x2f, p2, y2h);
    // 7) gemm-out: out = ELU(y2 * W2 + b2)
    gemm_bias_elu_kernel<C, false, false><<<GEMM_GRID, TPB>>>(
        y2h, W2h, b2, out, N_NODES, (const float*)nullptr, (const float*)nullptr,
        (float*)nullptr, (float*)nullptr);
}

// round 15
// speedup vs baseline: 1.1400x; 1.1400x over previous
#include <cuda_runtime.h>
#include <cuda_fp16.h>
#include <math.h>
#include <stdint.h>

#define N_NODES 20000
#define N_EDGES 640000
#define E_TOT   660000          // + self loops
#define H1      4
#define C       128
#define HC1     (H1 * C)        // 512

// ---------------- scratch (no allocations allowed) ----------------
__device__ __half g_xh[N_NODES * C];
__device__ __half g_W1s[HC1 * C];        // stacked+scaled: [512 x 128]
__device__ __half g_W2h[C * C];
__device__ __half g_yh[N_NODES * HC1];   // per-head aggregated x (normalized), fp16
__device__ __half g_x2h[N_NODES * C];
__device__ __half g_y2h[N_NODES * C];
__device__ float  g_p1[4 * E_TOT];       // layer-1 per-edge softmax numerators
__device__ float  g_p2[E_TOT];           // layer-2 per-edge numerators
__device__ float  g_as1[N_NODES * H1];
__device__ float  g_ad1[N_NODES * H1];
__device__ float  g_as2[N_NODES];
__device__ float  g_ad2[N_NODES];
__device__ float  g_was1[C * H1];
__device__ float  g_wad1[C * H1];
__device__ float  g_was2[C];
__device__ float  g_wad2[C];
__device__ int    g_rank[E_TOT];         // per-edge rank within its destination
__device__ int    g_rowptr[N_NODES + 1];
__device__ int    g_cnt[N_NODES];       // zero-initialized; scan re-zeroes after use
__device__ int    g_csrc[E_TOT + 1];    // +1 pad for unconditional prefetch

__device__ __forceinline__ unsigned int smem_u32(const void* p)
{
    return (unsigned int)__cvta_generic_to_shared(p);
}

// ================= prep: wfold + fp16 converts (x, W1s stacked, W2) + degree count/rank =================
__global__ __launch_bounds__(256) void prep_kernel(
    const float* __restrict__ x,  const float* __restrict__ W1,
    const float* __restrict__ W2, const float* __restrict__ as1,
    const float* __restrict__ ad1, const float* __restrict__ as2,
    const float* __restrict__ ad2, const int* __restrict__ ei,
    __half* __restrict__ xh, __half* __restrict__ W1s, __half* __restrict__ W2h,
    float* __restrict__ w_as1, float* __restrict__ w_ad1,
    float* __restrict__ w_as2, float* __restrict__ w_ad2,
    int* __restrict__ cnt, int* __restrict__ rank, int* __restrict__ csrc)
{
    const int R0 = N_NODES * C / 4;      // 640000  x -> xh
    const int R1 = HC1 * C / 4;          // 16384   W1 -> W1s (transposed blocks, 0.25x)
    const int R2 = C * C / 4;            // 4096    W2 -> W2h
    int gid = blockIdx.x * blockDim.x + threadIdx.x;

    if (gid == 0) csrc[E_TOT] = 0;      // prefetch pad

    if (gid < R0) {
        float4 v = ((const float4*)x)[gid];
        __half2* d2 = (__half2*)(xh + (size_t)gid * 4);
        d2[0] = __floats2half2_rn(v.x, v.y);
        d2[1] = __floats2half2_rn(v.z, v.w);
    } else if (gid < R0 + R1) {
        int m = gid - R0;
        int r = m >> 5;                  // row of W1s: 0..511
        int jc = (m & 31) * 4;           // col
        int h = r >> 7, i = r & 127;
        float4 v = *(const float4*)&W1[(size_t)i * HC1 + h * C + jc];
        __half2* d2 = (__half2*)(W1s + (size_t)r * C + jc);
        d2[0] = __floats2half2_rn(0.25f * v.x, 0.25f * v.y);
        d2[1] = __floats2half2_rn(0.25f * v.z, 0.25f * v.w);
    } else if (gid < R0 + R1 + R2) {
        int m = gid - R0 - R1;
        float4 v = ((const float4*)W2)[m];
        __half2* d2 = (__half2*)(W2h + (size_t)m * 4);
        d2[0] = __floats2half2_rn(v.x, v.y);
        d2[1] = __floats2half2_rn(v.z, v.w);
    }
    if (gid < E_TOT) {
        int d = (gid < N_EDGES) ? ei[N_EDGES + gid] : (gid - N_EDGES);
        rank[gid] = atomicAdd(&cnt[d], 1);   // rank reused by atomic-free scatter
    }
    int w = gid >> 5, lane = gid & 31;
    if (w < 512) {
        int k = w >> 2, h = w & 3;
        float4 wv = *(const float4*)&W1[(size_t)k * HC1 + h * C + lane * 4];
        float4 av = *(const float4*)&as1[h * C + lane * 4];
        float4 dv = *(const float4*)&ad1[h * C + lane * 4];
        float ss = wv.x * av.x + wv.y * av.y + wv.z * av.z + wv.w * av.w;
        float sd = wv.x * dv.x + wv.y * dv.y + wv.z * dv.z + wv.w * dv.w;
#pragma unroll
        for (int off = 16; off > 0; off >>= 1) {
            ss += __shfl_down_sync(0xffffffff, ss, off);
            sd += __shfl_down_sync(0xffffffff, sd, off);
        }
        if (lane == 0) { w_as1[k * H1 + h] = ss; w_ad1[k * H1 + h] = sd; }
    } else if (w < 640) {
        int k = w - 512;
        float4 wv = *(const float4*)&W2[(size_t)k * C + lane * 4];
        float4 av = *(const float4*)&as2[lane * 4];
        float4 dv = *(const float4*)&ad2[lane * 4];
        float ss = wv.x * av.x + wv.y * av.y + wv.z * av.z + wv.w * av.w;
        float sd = wv.x * dv.x + wv.y * dv.y + wv.z * dv.z + wv.w * dv.w;
#pragma unroll
        for (int off = 16; off > 0; off >>= 1) {
            ss += __shfl_down_sync(0xffffffff, ss, off);
            sd += __shfl_down_sync(0xffffffff, sd, off);
        }
        if (lane == 0) { w_as2[k] = ss; w_ad2[k] = sd; }
    }
}

// ================= coalesced smem-staged scan (1 block); zeroes cnt afterward =================
#define SCAN_ELEMS 20480   // 1024 * 20
__global__ __launch_bounds__(1024) void scan_kernel(
    int* __restrict__ cnt, int* __restrict__ rowptr)
{
    extern __shared__ int sm[];
    __shared__ int part[1024];
    const int t = threadIdx.x;
    const int CHUNK = 20;

    for (int i = t; i < SCAN_ELEMS; i += 1024)
        sm[i] = (i < N_NODES) ? cnt[i] : 0;
    __syncthreads();

    int base = t * CHUNK;
    int s = 0;
#pragma unroll
    for (int k = 0; k < CHUNK; k++) s += sm[base + k];
    part[t] = s;
    __syncthreads();
    for (int off = 1; off < 1024; off <<= 1) {
        int v = (t >= off) ? part[t - off] : 0;
        __syncthreads();
        part[t] += v;
        __syncthreads();
    }
    int run = part[t] - s;
#pragma unroll
    for (int k = 0; k < CHUNK; k++) {
        int c = sm[base + k];
        sm[base + k] = run;
        run += c;
    }
    __syncthreads();
    for (int i = t; i < N_NODES; i += 1024) {
        rowptr[i] = sm[i];
        cnt[i] = 0;
    }
    if (t == 1023) rowptr[N_NODES] = part[1023];
}

// ================= fused: atomic-free CSR scatter + layer-1 logits =================
#define SC_BLOCKS  ((E_TOT + 255) / 256)
#define AL_BLOCKS  ((N_NODES * 32 + 255) / 256)
__global__ __launch_bounds__(256) void fused_sa_kernel(
    const int* __restrict__ ei, const int* __restrict__ rowptr,
    const int* __restrict__ rank, int* __restrict__ csrc,
    const float* __restrict__ x, const float* __restrict__ w_as1,
    const float* __restrict__ w_ad1, float* __restrict__ as_o,
    float* __restrict__ ad_o)
{
    int bid = blockIdx.x;
    if (bid < SC_BLOCKS) {
        int i = bid * 256 + threadIdx.x;
        if (i < E_TOT) {
            int s, d;
            if (i < N_EDGES) { s = ei[i]; d = ei[N_EDGES + i]; }
            else { s = d = i - N_EDGES; }
            csrc[rowptr[d] + rank[i]] = s;   // no atomics: rank precomputed in prep
        }
        return;
    }
    bid -= SC_BLOCKS;
    {
        __shared__ float sw_s[C * H1], sw_d[C * H1];
        for (int i = threadIdx.x; i < C * H1; i += 256) {
            sw_s[i] = w_as1[i]; sw_d[i] = w_ad1[i];
        }
        __syncthreads();
        int n = (bid * 256 + threadIdx.x) >> 5;
        int lane = threadIdx.x & 31;
        if (n >= N_NODES) return;
        float4 xv = *(const float4*)&x[(size_t)n * C + lane * 4];
        float xs[4] = {xv.x, xv.y, xv.z, xv.w};
        float ps[4] = {0, 0, 0, 0}, pd[4] = {0, 0, 0, 0};
#pragma unroll
        for (int j = 0; j < 4; j++) {
            int k = lane * 4 + j;
#pragma unroll
            for (int h = 0; h < 4; h++) {
                ps[h] += xs[j] * sw_s[k * 4 + h];
                pd[h] += xs[j] * sw_d[k * 4 + h];
            }
        }
#pragma unroll
        for (int off = 16; off > 0; off >>= 1) {
#pragma unroll
            for (int h = 0; h < 4; h++) {
                ps[h] += __shfl_down_sync(0xffffffff, ps[h], off);
                pd[h] += __shfl_down_sync(0xffffffff, pd[h], off);
            }
        }
        if (lane == 0) {
            *(float4*)&as_o[n * 4] = make_float4(ps[0], ps[1], ps[2], ps[3]);
            *(float4*)&ad_o[n * 4] = make_float4(pd[0], pd[1], pd[2], pd[3]);
        }
    }
}

// ================= layer-1 aggregation, two-phase: exp once per edge, fp16 gather =================
__global__ __launch_bounds__(256) void agg1_kernel(
    const int* __restrict__ rowptr, const int* __restrict__ csrc,
    const float* __restrict__ as_v, const float* __restrict__ ad_v,
    const __half* __restrict__ xh, float* __restrict__ p1,
    __half* __restrict__ yh)
{
    int n = (blockIdx.x * 256 + threadIdx.x) >> 5;
    int lane = threadIdx.x & 31;
    if (n >= N_NODES) return;
    int start = rowptr[n], end = rowptr[n + 1];
    float4 adn = *(const float4*)&ad_v[n * 4];

    // ---- phase 1: per-edge softmax numerators (lanes parallel over edges) ----
    float d0 = 0.f, d1 = 0.f, d2 = 0.f, d3 = 0.f;
    for (int e = start + lane; e < end; e += 32) {
        int s = csrc[e];
        float4 lg = *(const float4*)&as_v[s * 4];
        float l0 = lg.x + adn.x; l0 = fmaxf(l0, 0.2f * l0);
        float l1 = lg.y + adn.y; l1 = fmaxf(l1, 0.2f * l1);
        float l2 = lg.z + adn.z; l2 = fmaxf(l2, 0.2f * l2);
        float l3 = lg.w + adn.w; l3 = fmaxf(l3, 0.2f * l3);
        float p0 = __expf(l0), pp1 = __expf(l1), p2 = __expf(l2), p3 = __expf(l3);
        *(float4*)&p1[(size_t)e * 4] = make_float4(p0, pp1, p2, p3);
        d0 += p0; d1 += pp1; d2 += p2; d3 += p3;
    }
#pragma unroll
    for (int off = 16; off > 0; off >>= 1) {
        d0 += __shfl_xor_sync(0xffffffff, d0, off);
        d1 += __shfl_xor_sync(0xffffffff, d1, off);
        d2 += __shfl_xor_sync(0xffffffff, d2, off);
        d3 += __shfl_xor_sync(0xffffffff, d3, off);
    }
    __syncwarp();                         // order p1 stores before phase-2 loads

    const int grp = lane >> 4;            // 0: heads 0/1, 1: heads 2/3
    const int sub = lane & 15;
    float invP = 1.f / (grp ? d2 : d0);
    float invQ = 1.f / (grp ? d3 : d1);

    // ---- phase 2: weighted gather-accumulate (no exp, no den) ----
    float accP[8], accQ[8];
#pragma unroll
    for (int j = 0; j < 8; j++) { accP[j] = 0.f; accQ[j] = 0.f; }

    int sA = csrc[start];                 // deg >= 1 (self loop)
    for (int e = start; e < end; e++) {
        int s = sA;
        sA = csrc[e + 1];                 // padded: always safe
        float2 pq = *(const float2*)&p1[(size_t)e * 4 + grp * 2];
        uint4 q = *(const uint4*)(xh + (size_t)s * C + sub * 8);
        const __half2* h = (const __half2*)&q;
#pragma unroll
        for (int j = 0; j < 4; j++) {
            float2 f = __half22float2(h[j]);
            accP[2*j]   += pq.x * f.x; accP[2*j+1] += pq.x * f.y;
            accQ[2*j]   += pq.y * f.x; accQ[2*j+1] += pq.y * f.y;
        }
    }
    __half hP[8], hQ[8];
#pragma unroll
    for (int j = 0; j < 8; j++) {
        hP[j] = __float2half(accP[j] * invP);
        hQ[j] = __float2half(accQ[j] * invQ);
    }
    *(uint4*)&yh[(size_t)n * HC1 + (grp * 2) * C + sub * 8]     = *(uint4*)hP;
    *(uint4*)&yh[(size_t)n * HC1 + (grp * 2 + 1) * C + sub * 8] = *(uint4*)hQ;
}

// ================= tensor-core GEMM + bias + ELU (+ optional layer-2 logits) =================
// C[M,128] = A[M,KDIM] * B[KDIM,128]; CTA 128x128, BK=64, 8 warps (4M x 2N)
template <int KDIM, bool OUT_HALF, bool DO_LOGITS>
__global__ __launch_bounds__(256) void gemm_bias_elu_kernel(
    const __half* __restrict__ A, const __half* __restrict__ B,
    const float* __restrict__ bias, void* __restrict__ Cout, int M,
    const float* __restrict__ w_s, const float* __restrict__ w_d,
    float* __restrict__ as_o, float* __restrict__ ad_o)
{
    __shared__ __half As[128][64];
    __shared__ __half Bs[64][128];
    __shared__ float sw_s[DO_LOGITS ? C : 1], sw_d[DO_LOGITS ? C : 1];
    __shared__ float redS[DO_LOGITS ? 128 : 1][2], redD[DO_LOGITS ? 128 : 1][2];

    const int tid = threadIdx.x;
    const int lane = tid & 31, wid = tid >> 5;
    const int warpM = wid >> 1, warpN = wid & 1;
    const int rowBase = blockIdx.x * 128;

    if (DO_LOGITS) {
        for (int i = tid; i < C; i += 256) { sw_s[i] = w_s[i]; sw_d[i] = w_d[i]; }
    }

    float acc[2][8][4];
#pragma unroll
    for (int mi = 0; mi < 2; mi++)
#pragma unroll
        for (int ni = 0; ni < 8; ni++)
#pragma unroll
            for (int q = 0; q < 4; q++) acc[mi][ni][q] = 0.f;

    const int arow0 = warpM * 32 + (lane & 15);
    const int brow0 = (lane & 15);
    const int hi = (lane >> 4);

    for (int kt = 0; kt < KDIM / 64; kt++) {
#pragma unroll
        for (int i = tid; i < 1024; i += 256) {
            int r = i >> 3, ch = i & 7;
            int gr = rowBase + r;
            uint4 v = make_uint4(0u, 0u, 0u, 0u);
            if (gr < M) v = *(const uint4*)&A[(size_t)gr * KDIM + kt * 64 + ch * 8];
            int sch = ch ^ (r & 7);
            *(uint4*)&As[r][sch * 8] = v;
        }
#pragma unroll
        for (int i = tid; i < 1024; i += 256) {
            int r = i >> 4, ch = i & 15;
            uint4 v = *(const uint4*)&B[(size_t)(kt * 64 + r) * C + ch * 8];
            int sch = (ch & 8) | ((ch & 7) ^ (r & 7));
            *(uint4*)&Bs[r][sch * 8] = v;
        }
        __syncthreads();

#pragma unroll
        for (int kk = 0; kk < 4; kk++) {
            unsigned int a[2][4];
#pragma unroll
            for (int mi = 0; mi < 2; mi++) {
                int r = arow0 + mi * 16;
                int ch = (kk * 2 + hi) ^ (r & 7);
                unsigned int addr = smem_u32(&As[r][ch * 8]);
                asm volatile("ldmatrix.sync.aligned.m8n8.x4.shared.b16 {%0,%1,%2,%3}, [%4];"
                    : "=r"(a[mi][0]), "=r"(a[mi][1]), "=r"(a[mi][2]), "=r"(a[mi][3])
                    : "r"(addr));
            }
            unsigned int b[8][2];
#pragma unroll
            for (int np = 0; np < 4; np++) {
                int r = kk * 16 + brow0;
                int chL = warpN * 8 + np * 2 + hi;
                int ch = (chL & 8) | ((chL & 7) ^ (r & 7));
                unsigned int addr = smem_u32(&Bs[r][ch * 8]);
                unsigned int r0, r1, r2, r3;
                asm volatile("ldmatrix.sync.aligned.m8n8.x4.trans.shared.b16 {%0,%1,%2,%3}, [%4];"
                    : "=r"(r0), "=r"(r1), "=r"(r2), "=r"(r3) : "r"(addr));
                b[np * 2][0] = r0;     b[np * 2][1] = r1;
                b[np * 2 + 1][0] = r2; b[np * 2 + 1][1] = r3;
            }
#pragma unroll
            for (int mi = 0; mi < 2; mi++)
#pragma unroll
                for (int ni = 0; ni < 8; ni++)
                    asm volatile(
                        "mma.sync.aligned.m16n8k16.row.col.f32.f16.f16.f32 "
                        "{%0,%1,%2,%3},{%4,%5,%6,%7},{%8,%9},{%0,%1,%2,%3};"
                        : "+f"(acc[mi][ni][0]), "+f"(acc[mi][ni][1]),
                          "+f"(acc[mi][ni][2]), "+f"(acc[mi][ni][3])
                        : "r"(a[mi][0]), "r"(a[mi][1]), "r"(a[mi][2]), "r"(a[mi][3]),
                          "r"(b[ni][0]), "r"(b[ni][1]));
        }
        __syncthreads();
    }

    // ---- epilogue: bias + ELU (+ logits) ----
    float psum[2][2], pdum[2][2];
    if (DO_LOGITS) {
        psum[0][0] = psum[0][1] = psum[1][0] = psum[1][1] = 0.f;
        pdum[0][0] = pdum[0][1] = pdum[1][0] = pdum[1][1] = 0.f;
    }
#pragma unroll
    for (int mi = 0; mi < 2; mi++) {
        int r0 = rowBase + warpM * 32 + mi * 16 + (lane >> 2);
#pragma unroll
        for (int ni = 0; ni < 8; ni++) {
            int col = warpN * 64 + ni * 8 + (lane & 3) * 2;
            float b0 = bias[col], b1v = bias[col + 1];
            float v0 = acc[mi][ni][0] + b0;  v0 = v0 > 0.f ? v0 : expm1f(v0);
            float v1 = acc[mi][ni][1] + b1v; v1 = v1 > 0.f ? v1 : expm1f(v1);
            float v2 = acc[mi][ni][2] + b0;  v2 = v2 > 0.f ? v2 : expm1f(v2);
            float v3 = acc[mi][ni][3] + b1v; v3 = v3 > 0.f ? v3 : expm1f(v3);
            if (DO_LOGITS) {
                psum[mi][0] += v0 * sw_s[col] + v1 * sw_s[col + 1];
                psum[mi][1] += v2 * sw_s[col] + v3 * sw_s[col + 1];
                pdum[mi][0] += v0 * sw_d[col] + v1 * sw_d[col + 1];
                pdum[mi][1] += v2 * sw_d[col] + v3 * sw_d[col + 1];
            }
            if (OUT_HALF) {
                __half* Ch = (__half*)Cout;
                if (r0 < M)
                    *(__half2*)&Ch[(size_t)r0 * C + col] = __floats2half2_rn(v0, v1);
                if (r0 + 8 < M)
                    *(__half2*)&Ch[(size_t)(r0 + 8) * C + col] = __floats2half2_rn(v2, v3);
            } else {
                float* Cf = (float*)Cout;
                if (r0 < M)
                    *(float2*)&Cf[(size_t)r0 * C + col] = make_float2(v0, v1);
                if (r0 + 8 < M)
                    *(float2*)&Cf[(size_t)(r0 + 8) * C + col] = make_float2(v2, v3);
            }
        }
    }
    if (DO_LOGITS) {
#pragma unroll
        for (int mi = 0; mi < 2; mi++)
#pragma unroll
            for (int rh = 0; rh < 2; rh++) {
                float s = psum[mi][rh], d = pdum[mi][rh];
                s += __shfl_xor_sync(0xffffffff, s, 1);
                s += __shfl_xor_sync(0xffffffff, s, 2);
                d += __shfl_xor_sync(0xffffffff, d, 1);
                d += __shfl_xor_sync(0xffffffff, d, 2);
                if ((lane & 3) == 0) {
                    int lr = warpM * 32 + mi * 16 + rh * 8 + (lane >> 2);
                    redS[lr][warpN] = s;
                    redD[lr][warpN] = d;
                }
            }
        __syncthreads();
        if (tid < 128) {
            int rg = rowBase + tid;
            if (rg < M) {
                as_o[rg] = redS[tid][0] + redS[tid][1];
                ad_o[rg] = redD[tid][0] + redD[tid][1];
            }
        }
    }
}

// ================= layer-2 aggregation, two-phase =================
__global__ __launch_bounds__(256) void agg2_kernel(
    const int* __restrict__ rowptr, const int* __restrict__ csrc,
    const float* __restrict__ as_v, const float* __restrict__ ad_v,
    const __half* __restrict__ x2h, float* __restrict__ p2,
    __half* __restrict__ y2h)
{
    int n = (blockIdx.x * 256 + threadIdx.x) >> 5;
    int lane = threadIdx.x & 31;
    if (n >= N_NODES) return;
    int start = rowptr[n], end = rowptr[n + 1];
    float adn = ad_v[n];

    // ---- phase 1: per-edge numerators ----
    float den = 0.f;
    for (int e = start + lane; e < end; e += 32) {
        int s = csrc[e];
        float l = as_v[s] + adn;
        l = fmaxf(l, 0.2f * l);
        float p = __expf(l);
        p2[e] = p;
        den += p;
    }
#pragma unroll
    for (int off = 16; off > 0; off >>= 1)
        den += __shfl_xor_sync(0xffffffff, den, off);
    __syncwarp();
    float inv = 1.f / den;

    // ---- phase 2: weighted gather-accumulate ----
    float ax = 0.f, ay = 0.f, az = 0.f, aw = 0.f;
    int sA = csrc[start];
    for (int e = start; e < end; e++) {
        int s = sA;
        sA = csrc[e + 1];
        float p = p2[e];
        uint2 q = *(const uint2*)(x2h + (size_t)s * C + lane * 4);
        const __half2* h = (const __half2*)&q;
        float2 f0 = __half22float2(h[0]), f1 = __half22float2(h[1]);
        ax += p * f0.x; ay += p * f0.y; az += p * f1.x; aw += p * f1.y;
    }
    __half2 o0 = __floats2half2_rn(ax * inv, ay * inv);
    __half2 o1 = __floats2half2_rn(az * inv, aw * inv);
    uint2 o; o.x = *(unsigned int*)&o0; o.y = *(unsigned int*)&o1;
    *(uint2*)&y2h[(size_t)n * C + lane * 4] = o;
}

// ---------------- launch ----------------
extern "C" void kernel_launch(void* const* d_in, const int* in_sizes, int n_in,
                              void* d_out, int out_size)
{
    const float* x      = (const float*)d_in[0];
    const float* W1     = (const float*)d_in[1];
    const float* a_src1 = (const float*)d_in[2];
    const float* a_dst1 = (const float*)d_in[3];
    const float* b1     = (const float*)d_in[4];
    const float* W2     = (const float*)d_in[5];
    const float* a_src2 = (const float*)d_in[6];
    const float* a_dst2 = (const float*)d_in[7];
    const float* b2     = (const float*)d_in[8];
    const int*   ei     = (const int*)d_in[9];
    float* out = (float*)d_out;

    __half *xh, *W1s, *W2h, *yh, *x2h, *y2h;
    float *p1, *p2, *as1, *ad1, *as2, *ad2, *was1, *wad1, *was2, *wad2;
    int *rowptr, *cnt, *csrc, *rankp;
    cudaGetSymbolAddress((void**)&xh,     g_xh);
    cudaGetSymbolAddress((void**)&W1s,    g_W1s);
    cudaGetSymbolAddress((void**)&W2h,    g_W2h);
    cudaGetSymbolAddress((void**)&yh,     g_yh);
    cudaGetSymbolAddress((void**)&x2h,    g_x2h);
    cudaGetSymbolAddress((void**)&y2h,    g_y2h);
    cudaGetSymbolAddress((void**)&p1,     g_p1);
    cudaGetSymbolAddress((void**)&p2,     g_p2);
    cudaGetSymbolAddress((void**)&as1,    g_as1);
    cudaGetSymbolAddress((void**)&ad1,    g_ad1);
    cudaGetSymbolAddress((void**)&as2,    g_as2);
    cudaGetSymbolAddress((void**)&ad2,    g_ad2);
    cudaGetSymbolAddress((void**)&was1,   g_was1);
    cudaGetSymbolAddress((void**)&wad1,   g_wad1);
    cudaGetSymbolAddress((void**)&was2,   g_was2);
    cudaGetSymbolAddress((void**)&wad2,   g_wad2);
    cudaGetSymbolAddress((void**)&rankp,  g_rank);
    cudaGetSymbolAddress((void**)&rowptr, g_rowptr);
    cudaGetSymbolAddress((void**)&cnt,    g_cnt);
    cudaGetSymbolAddress((void**)&csrc,   g_csrc);

    const int TPB = 256;
    const int PREP_TOTAL = N_NODES * C / 4 + HC1 * C / 4 + C * C / 4;   // 660480
    int prep_blocks = (PREP_TOTAL + TPB - 1) / TPB;
    if (prep_blocks < (E_TOT + TPB - 1) / TPB) prep_blocks = (E_TOT + TPB - 1) / TPB;

    cudaFuncSetAttribute(scan_kernel, cudaFuncAttributeMaxDynamicSharedMemorySize,
                         SCAN_ELEMS * (int)sizeof(int));

    const int GEMM_GRID = (N_NODES + 127) / 128;   // 157
    const int WARP_GRID = (N_NODES * 32 + TPB - 1) / TPB;

    // 1) prep: wfold + converts + count/rank (+ csrc pad)
    prep_kernel<<<prep_blocks, TPB>>>(x, W1, W2, a_src1, a_dst1, a_src2, a_dst2, ei,
                                      xh, W1s, W2h, was1, wad1, was2, wad2,
                                      cnt, rankp, csrc);
    // 2) scan
    scan_kernel<<<1, 1024, SCAN_ELEMS * sizeof(int)>>>(cnt, rowptr);
    // 3) fused: atomic-free scatter + alphas1
    fused_sa_kernel<<<SC_BLOCKS + AL_BLOCKS, TPB>>>(
        ei, rowptr, rankp, csrc, x, was1, wad1, as1, ad1);
    // 4) layer-1 aggregation (two-phase) -> yh
    agg1_kernel<<<WARP_GRID, TPB>>>(rowptr, csrc, as1, ad1, xh, p1, yh);
    // 5) gemm-mid: x2 = ELU(yh * W1s + b1) fp16; epilogue computes layer-2 logits
    gemm_bias_elu_kernel<HC1, true, true><<<GEMM_GRID, TPB>>>(
        yh, W1s, b1, x2h, N_NODES, was2, wad2, as2, ad2);
    // 6) layer-2 aggregation (two-phase) -> y2
    agg2_kernel<<<WARP_GRID, TPB>>>(rowptr, csrc, as2, ad2, x2h, p2, y2h);
    // 7) gemm-out: out = ELU(y2 * W2 + b2)
    gemm_bias_elu_kernel<C, false, false><<<GEMM_GRID, TPB>>>(
        y2h, W2h, b2, out, N_NODES, (const float*)nullptr, (const float*)nullptr,
        (float*)nullptr, (float*)nullptr);
}

// round 16
// speedup vs baseline: 1.2055x; 1.0575x over previous
#include <cuda_runtime.h>
#include <cuda_fp16.h>
#include <math.h>
#include <stdint.h>

#define N_NODES 20000
#define N_EDGES 640000
#define E_TOT   660000          // + self loops
#define H1      4
#define C       128
#define HC1     (H1 * C)        // 512

// ---------------- scratch (no allocations allowed) ----------------
__device__ __half g_xh[N_NODES * C];
__device__ __half g_W1s[HC1 * C];        // stacked+scaled: [512 x 128]
__device__ __half g_W2h[C * C];
__device__ __half g_yh[N_NODES * HC1];   // per-head aggregated x (normalized), fp16
__device__ __half g_x2h[N_NODES * C];
__device__ __half g_y2h[N_NODES * C];
__device__ float  g_p1[4 * E_TOT];       // layer-1 per-edge softmax numerators
__device__ float  g_p2[E_TOT];           // layer-2 per-edge numerators
__device__ float  g_as1[N_NODES * H1];
__device__ float  g_ad1[N_NODES * H1];
__device__ float  g_as2[N_NODES];
__device__ float  g_ad2[N_NODES];
__device__ float  g_was1[C * H1];
__device__ float  g_wad1[C * H1];
__device__ float  g_was2[C];
__device__ float  g_wad2[C];
__device__ int    g_rank[E_TOT];         // per-edge rank within its destination
__device__ int    g_rowptr[N_NODES + 1];
__device__ int    g_cnt[N_NODES];       // zero-initialized; scan re-zeroes after use
__device__ int    g_csrc[E_TOT];

__device__ __forceinline__ unsigned int smem_u32(const void* p)
{
    return (unsigned int)__cvta_generic_to_shared(p);
}

// ================= prep: wfold + fp16 converts (x, W1s stacked, W2) + degree count/rank =================
__global__ __launch_bounds__(256) void prep_kernel(
    const float* __restrict__ x,  const float* __restrict__ W1,
    const float* __restrict__ W2, const float* __restrict__ as1,
    const float* __restrict__ ad1, const float* __restrict__ as2,
    const float* __restrict__ ad2, const int* __restrict__ ei,
    __half* __restrict__ xh, __half* __restrict__ W1s, __half* __restrict__ W2h,
    float* __restrict__ w_as1, float* __restrict__ w_ad1,
    float* __restrict__ w_as2, float* __restrict__ w_ad2,
    int* __restrict__ cnt, int* __restrict__ rank)
{
    const int R0 = N_NODES * C / 4;      // 640000  x -> xh
    const int R1 = HC1 * C / 4;          // 16384   W1 -> W1s (transposed blocks, 0.25x)
    const int R2 = C * C / 4;            // 4096    W2 -> W2h
    int gid = blockIdx.x * blockDim.x + threadIdx.x;

    if (gid < R0) {
        float4 v = ((const float4*)x)[gid];
        __half2* d2 = (__half2*)(xh + (size_t)gid * 4);
        d2[0] = __floats2half2_rn(v.x, v.y);
        d2[1] = __floats2half2_rn(v.z, v.w);
    } else if (gid < R0 + R1) {
        int m = gid - R0;
        int r = m >> 5;                  // row of W1s: 0..511
        int jc = (m & 31) * 4;           // col
        int h = r >> 7, i = r & 127;
        float4 v = *(const float4*)&W1[(size_t)i * HC1 + h * C + jc];
        __half2* d2 = (__half2*)(W1s + (size_t)r * C + jc);
        d2[0] = __floats2half2_rn(0.25f * v.x, 0.25f * v.y);
        d2[1] = __floats2half2_rn(0.25f * v.z, 0.25f * v.w);
    } else if (gid < R0 + R1 + R2) {
        int m = gid - R0 - R1;
        float4 v = ((const float4*)W2)[m];
        __half2* d2 = (__half2*)(W2h + (size_t)m * 4);
        d2[0] = __floats2half2_rn(v.x, v.y);
        d2[1] = __floats2half2_rn(v.z, v.w);
    }
    if (gid < E_TOT) {
        int d = (gid < N_EDGES) ? ei[N_EDGES + gid] : (gid - N_EDGES);
        rank[gid] = atomicAdd(&cnt[d], 1);   // rank reused by atomic-free scatter
    }
    int w = gid >> 5, lane = gid & 31;
    if (w < 512) {
        int k = w >> 2, h = w & 3;
        float4 wv = *(const float4*)&W1[(size_t)k * HC1 + h * C + lane * 4];
        float4 av = *(const float4*)&as1[h * C + lane * 4];
        float4 dv = *(const float4*)&ad1[h * C + lane * 4];
        float ss = wv.x * av.x + wv.y * av.y + wv.z * av.z + wv.w * av.w;
        float sd = wv.x * dv.x + wv.y * dv.y + wv.z * dv.z + wv.w * dv.w;
#pragma unroll
        for (int off = 16; off > 0; off >>= 1) {
            ss += __shfl_down_sync(0xffffffff, ss, off);
            sd += __shfl_down_sync(0xffffffff, sd, off);
        }
        if (lane == 0) { w_as1[k * H1 + h] = ss; w_ad1[k * H1 + h] = sd; }
    } else if (w < 640) {
        int k = w - 512;
        float4 wv = *(const float4*)&W2[(size_t)k * C + lane * 4];
        float4 av = *(const float4*)&as2[lane * 4];
        float4 dv = *(const float4*)&ad2[lane * 4];
        float ss = wv.x * av.x + wv.y * av.y + wv.z * av.z + wv.w * av.w;
        float sd = wv.x * dv.x + wv.y * dv.y + wv.z * dv.z + wv.w * dv.w;
#pragma unroll
        for (int off = 16; off > 0; off >>= 1) {
            ss += __shfl_down_sync(0xffffffff, ss, off);
            sd += __shfl_down_sync(0xffffffff, sd, off);
        }
        if (lane == 0) { w_as2[k] = ss; w_ad2[k] = sd; }
    }
}

// ================= coalesced smem-staged scan (1 block); zeroes cnt afterward =================
#define SCAN_ELEMS 20480   // 1024 * 20
__global__ __launch_bounds__(1024) void scan_kernel(
    int* __restrict__ cnt, int* __restrict__ rowptr)
{
    extern __shared__ int sm[];
    __shared__ int part[1024];
    const int t = threadIdx.x;
    const int CHUNK = 20;

    for (int i = t; i < SCAN_ELEMS; i += 1024)
        sm[i] = (i < N_NODES) ? cnt[i] : 0;
    __syncthreads();

    int base = t * CHUNK;
    int s = 0;
#pragma unroll
    for (int k = 0; k < CHUNK; k++) s += sm[base + k];
    part[t] = s;
    __syncthreads();
    for (int off = 1; off < 1024; off <<= 1) {
        int v = (t >= off) ? part[t - off] : 0;
        __syncthreads();
        part[t] += v;
        __syncthreads();
    }
    int run = part[t] - s;
#pragma unroll
    for (int k = 0; k < CHUNK; k++) {
        int c = sm[base + k];
        sm[base + k] = run;
        run += c;
    }
    __syncthreads();
    for (int i = t; i < N_NODES; i += 1024) {
        rowptr[i] = sm[i];
        cnt[i] = 0;
    }
    if (t == 1023) rowptr[N_NODES] = part[1023];
}

// ================= fused: atomic-free CSR scatter + layer-1 logits =================
#define SC_BLOCKS  ((E_TOT + 255) / 256)
#define AL_BLOCKS  ((N_NODES * 32 + 255) / 256)
__global__ __launch_bounds__(256) void fused_sa_kernel(
    const int* __restrict__ ei, const int* __restrict__ rowptr,
    const int* __restrict__ rank, int* __restrict__ csrc,
    const float* __restrict__ x, const float* __restrict__ w_as1,
    const float* __restrict__ w_ad1, float* __restrict__ as_o,
    float* __restrict__ ad_o)
{
    int bid = blockIdx.x;
    if (bid < SC_BLOCKS) {
        int i = bid * 256 + threadIdx.x;
        if (i < E_TOT) {
            int s, d;
            if (i < N_EDGES) { s = ei[i]; d = ei[N_EDGES + i]; }
            else { s = d = i - N_EDGES; }
            csrc[rowptr[d] + rank[i]] = s;   // no atomics: rank precomputed in prep
        }
        return;
    }
    bid -= SC_BLOCKS;
    {
        __shared__ float sw_s[C * H1], sw_d[C * H1];
        for (int i = threadIdx.x; i < C * H1; i += 256) {
            sw_s[i] = w_as1[i]; sw_d[i] = w_ad1[i];
        }
        __syncthreads();
        int n = (bid * 256 + threadIdx.x) >> 5;
        int lane = threadIdx.x & 31;
        if (n >= N_NODES) return;
        float4 xv = *(const float4*)&x[(size_t)n * C + lane * 4];
        float xs[4] = {xv.x, xv.y, xv.z, xv.w};
        float ps[4] = {0, 0, 0, 0}, pd[4] = {0, 0, 0, 0};
#pragma unroll
        for (int j = 0; j < 4; j++) {
            int k = lane * 4 + j;
#pragma unroll
            for (int h = 0; h < 4; h++) {
                ps[h] += xs[j] * sw_s[k * 4 + h];
                pd[h] += xs[j] * sw_d[k * 4 + h];
            }
        }
#pragma unroll
        for (int off = 16; off > 0; off >>= 1) {
#pragma unroll
            for (int h = 0; h < 4; h++) {
                ps[h] += __shfl_down_sync(0xffffffff, ps[h], off);
                pd[h] += __shfl_down_sync(0xffffffff, pd[h], off);
            }
        }
        if (lane == 0) {
            *(float4*)&as_o[n * 4] = make_float4(ps[0], ps[1], ps[2], ps[3]);
            *(float4*)&ad_o[n * 4] = make_float4(pd[0], pd[1], pd[2], pd[3]);
        }
    }
}

// ================= layer-1 aggregation, two-phase; lane = 4ch x 4 heads; 2-edge unroll =================
__global__ __launch_bounds__(256) void agg1_kernel(
    const int* __restrict__ rowptr, const int* __restrict__ csrc,
    const float* __restrict__ as_v, const float* __restrict__ ad_v,
    const __half* __restrict__ xh, float* __restrict__ p1,
    __half* __restrict__ yh)
{
    int n = (blockIdx.x * 256 + threadIdx.x) >> 5;
    int lane = threadIdx.x & 31;
    if (n >= N_NODES) return;
    int start = rowptr[n], end = rowptr[n + 1];
    float4 adn = *(const float4*)&ad_v[n * 4];

    // ---- phase 1: per-edge softmax numerators (lanes parallel over edges) ----
    float d0 = 0.f, d1 = 0.f, d2 = 0.f, d3 = 0.f;
    for (int e = start + lane; e < end; e += 32) {
        int s = csrc[e];
        float4 lg = *(const float4*)&as_v[s * 4];
        float l0 = lg.x + adn.x; l0 = fmaxf(l0, 0.2f * l0);
        float l1 = lg.y + adn.y; l1 = fmaxf(l1, 0.2f * l1);
        float l2 = lg.z + adn.z; l2 = fmaxf(l2, 0.2f * l2);
        float l3 = lg.w + adn.w; l3 = fmaxf(l3, 0.2f * l3);
        float p0 = __expf(l0), pp1 = __expf(l1), p2 = __expf(l2), p3 = __expf(l3);
        *(float4*)&p1[(size_t)e * 4] = make_float4(p0, pp1, p2, p3);
        d0 += p0; d1 += pp1; d2 += p2; d3 += p3;
    }
#pragma unroll
    for (int off = 16; off > 0; off >>= 1) {
        d0 += __shfl_xor_sync(0xffffffff, d0, off);
        d1 += __shfl_xor_sync(0xffffffff, d1, off);
        d2 += __shfl_xor_sync(0xffffffff, d2, off);
        d3 += __shfl_xor_sync(0xffffffff, d3, off);
    }
    __syncwarp();                         // order p1 stores before phase-2 loads

    // ---- phase 2: lane owns channels [lane*4, lane*4+4), all 4 heads; 2-edge unroll ----
    float acc[4][4];
#pragma unroll
    for (int h = 0; h < 4; h++)
#pragma unroll
        for (int j = 0; j < 4; j++) acc[h][j] = 0.f;

    const __half* xcol = xh + lane * 4;
    int e = start;
    for (; e + 1 < end; e += 2) {
        int s0 = csrc[e], s1 = csrc[e + 1];
        float4 pa = *(const float4*)&p1[(size_t)e * 4];
        float4 pb = *(const float4*)&p1[(size_t)(e + 1) * 4];
        uint2 q0 = *(const uint2*)(xcol + (size_t)s0 * C);
        uint2 q1 = *(const uint2*)(xcol + (size_t)s1 * C);
        float2 f00 = __half22float2(((const __half2*)&q0)[0]);
        float2 f01 = __half22float2(((const __half2*)&q0)[1]);
        float2 f10 = __half22float2(((const __half2*)&q1)[0]);
        float2 f11 = __half22float2(((const __half2*)&q1)[1]);
        float fa[4] = {f00.x, f00.y, f01.x, f01.y};
        float fb[4] = {f10.x, f10.y, f11.x, f11.y};
        float pav[4] = {pa.x, pa.y, pa.z, pa.w};
        float pbv[4] = {pb.x, pb.y, pb.z, pb.w};
#pragma unroll
        for (int h = 0; h < 4; h++)
#pragma unroll
            for (int j = 0; j < 4; j++)
                acc[h][j] += pav[h] * fa[j] + pbv[h] * fb[j];
    }
    if (e < end) {
        int s0 = csrc[e];
        float4 pa = *(const float4*)&p1[(size_t)e * 4];
        uint2 q0 = *(const uint2*)(xcol + (size_t)s0 * C);
        float2 f00 = __half22float2(((const __half2*)&q0)[0]);
        float2 f01 = __half22float2(((const __half2*)&q0)[1]);
        float fa[4] = {f00.x, f00.y, f01.x, f01.y};
        float pav[4] = {pa.x, pa.y, pa.z, pa.w};
#pragma unroll
        for (int h = 0; h < 4; h++)
#pragma unroll
            for (int j = 0; j < 4; j++)
                acc[h][j] += pav[h] * fa[j];
    }

    float invs[4] = {1.f / d0, 1.f / d1, 1.f / d2, 1.f / d3};
#pragma unroll
    for (int h = 0; h < 4; h++) {
        __half hv[4];
#pragma unroll
        for (int j = 0; j < 4; j++) hv[j] = __float2half(acc[h][j] * invs[h]);
        *(uint2*)&yh[(size_t)n * HC1 + h * C + lane * 4] = *(uint2*)hv;
    }
}

// ================= tensor-core GEMM + bias + ELU (+ optional layer-2 logits) =================
// C[M,128] = A[M,KDIM] * B[KDIM,128]; CTA 128x128, BK=64, 8 warps (4M x 2N)
template <int KDIM, bool OUT_HALF, bool DO_LOGITS>
__global__ __launch_bounds__(256) void gemm_bias_elu_kernel(
    const __half* __restrict__ A, const __half* __restrict__ B,
    const float* __restrict__ bias, void* __restrict__ Cout, int M,
    const float* __restrict__ w_s, const float* __restrict__ w_d,
    float* __restrict__ as_o, float* __restrict__ ad_o)
{
    __shared__ __half As[128][64];
    __shared__ __half Bs[64][128];
    __shared__ float sw_s[DO_LOGITS ? C : 1], sw_d[DO_LOGITS ? C : 1];
    __shared__ float redS[DO_LOGITS ? 128 : 1][2], redD[DO_LOGITS ? 128 : 1][2];

    const int tid = threadIdx.x;
    const int lane = tid & 31, wid = tid >> 5;
    const int warpM = wid >> 1, warpN = wid & 1;
    const int rowBase = blockIdx.x * 128;

    if (DO_LOGITS) {
        for (int i = tid; i < C; i += 256) { sw_s[i] = w_s[i]; sw_d[i] = w_d[i]; }
    }

    float acc[2][8][4];
#pragma unroll
    for (int mi = 0; mi < 2; mi++)
#pragma unroll
        for (int ni = 0; ni < 8; ni++)
#pragma unroll
            for (int q = 0; q < 4; q++) acc[mi][ni][q] = 0.f;

    const int arow0 = warpM * 32 + (lane & 15);
    const int brow0 = (lane & 15);
    const int hi = (lane >> 4);

    for (int kt = 0; kt < KDIM / 64; kt++) {
#pragma unroll
        for (int i = tid; i < 1024; i += 256) {
            int r = i >> 3, ch = i & 7;
            int gr = rowBase + r;
            uint4 v = make_uint4(0u, 0u, 0u, 0u);
            if (gr < M) v = *(const uint4*)&A[(size_t)gr * KDIM + kt * 64 + ch * 8];
            int sch = ch ^ (r & 7);
            *(uint4*)&As[r][sch * 8] = v;
        }
#pragma unroll
        for (int i = tid; i < 1024; i += 256) {
            int r = i >> 4, ch = i & 15;
            uint4 v = *(const uint4*)&B[(size_t)(kt * 64 + r) * C + ch * 8];
            int sch = (ch & 8) | ((ch & 7) ^ (r & 7));
            *(uint4*)&Bs[r][sch * 8] = v;
        }
        __syncthreads();

#pragma unroll
        for (int kk = 0; kk < 4; kk++) {
            unsigned int a[2][4];
#pragma unroll
            for (int mi = 0; mi < 2; mi++) {
                int r = arow0 + mi * 16;
                int ch = (kk * 2 + hi) ^ (r & 7);
                unsigned int addr = smem_u32(&As[r][ch * 8]);
                asm volatile("ldmatrix.sync.aligned.m8n8.x4.shared.b16 {%0,%1,%2,%3}, [%4];"
                    : "=r"(a[mi][0]), "=r"(a[mi][1]), "=r"(a[mi][2]), "=r"(a[mi][3])
                    : "r"(addr));
            }
            unsigned int b[8][2];
#pragma unroll
            for (int np = 0; np < 4; np++) {
                int r = kk * 16 + brow0;
                int chL = warpN * 8 + np * 2 + hi;
                int ch = (chL & 8) | ((chL & 7) ^ (r & 7));
                unsigned int addr = smem_u32(&Bs[r][ch * 8]);
                unsigned int r0, r1, r2, r3;
                asm volatile("ldmatrix.sync.aligned.m8n8.x4.trans.shared.b16 {%0,%1,%2,%3}, [%4];"
                    : "=r"(r0), "=r"(r1), "=r"(r2), "=r"(r3) : "r"(addr));
                b[np * 2][0] = r0;     b[np * 2][1] = r1;
                b[np * 2 + 1][0] = r2; b[np * 2 + 1][1] = r3;
            }
#pragma unroll
            for (int mi = 0; mi < 2; mi++)
#pragma unroll
                for (int ni = 0; ni < 8; ni++)
                    asm volatile(
                        "mma.sync.aligned.m16n8k16.row.col.f32.f16.f16.f32 "
                        "{%0,%1,%2,%3},{%4,%5,%6,%7},{%8,%9},{%0,%1,%2,%3};"
                        : "+f"(acc[mi][ni][0]), "+f"(acc[mi][ni][1]),
                          "+f"(acc[mi][ni][2]), "+f"(acc[mi][ni][3])
                        : "r"(a[mi][0]), "r"(a[mi][1]), "r"(a[mi][2]), "r"(a[mi][3]),
                          "r"(b[ni][0]), "r"(b[ni][1]));
        }
        __syncthreads();
    }

    // ---- epilogue: bias + ELU (+ logits) ----
    float psum[2][2], pdum[2][2];
    if (DO_LOGITS) {
        psum[0][0] = psum[0][1] = psum[1][0] = psum[1][1] = 0.f;
        pdum[0][0] = pdum[0][1] = pdum[1][0] = pdum[1][1] = 0.f;
    }
#pragma unroll
    for (int mi = 0; mi < 2; mi++) {
        int r0 = rowBase + warpM * 32 + mi * 16 + (lane >> 2);
#pragma unroll
        for (int ni = 0; ni < 8; ni++) {
            int col = warpN * 64 + ni * 8 + (lane & 3) * 2;
            float b0 = bias[col], b1v = bias[col + 1];
            float v0 = acc[mi][ni][0] + b0;  v0 = v0 > 0.f ? v0 : expm1f(v0);
            float v1 = acc[mi][ni][1] + b1v; v1 = v1 > 0.f ? v1 : expm1f(v1);
            float v2 = acc[mi][ni][2] + b0;  v2 = v2 > 0.f ? v2 : expm1f(v2);
            float v3 = acc[mi][ni][3] + b1v; v3 = v3 > 0.f ? v3 : expm1f(v3);
            if (DO_LOGITS) {
                psum[mi][0] += v0 * sw_s[col] + v1 * sw_s[col + 1];
                psum[mi][1] += v2 * sw_s[col] + v3 * sw_s[col + 1];
                pdum[mi][0] += v0 * sw_d[col] + v1 * sw_d[col + 1];
                pdum[mi][1] += v2 * sw_d[col] + v3 * sw_d[col + 1];
            }
            if (OUT_HALF) {
                __half* Ch = (__half*)Cout;
                if (r0 < M)
                    *(__half2*)&Ch[(size_t)r0 * C + col] = __floats2half2_rn(v0, v1);
                if (r0 + 8 < M)
                    *(__half2*)&Ch[(size_t)(r0 + 8) * C + col] = __floats2half2_rn(v2, v3);
            } else {
                float* Cf = (float*)Cout;
                if (r0 < M)
                    *(float2*)&Cf[(size_t)r0 * C + col] = make_float2(v0, v1);
                if (r0 + 8 < M)
                    *(float2*)&Cf[(size_t)(r0 + 8) * C + col] = make_float2(v2, v3);
            }
        }
    }
    if (DO_LOGITS) {
#pragma unroll
        for (int mi = 0; mi < 2; mi++)
#pragma unroll
            for (int rh = 0; rh < 2; rh++) {
                float s = psum[mi][rh], d = pdum[mi][rh];
                s += __shfl_xor_sync(0xffffffff, s, 1);
                s += __shfl_xor_sync(0xffffffff, s, 2);
                d += __shfl_xor_sync(0xffffffff, d, 1);
                d += __shfl_xor_sync(0xffffffff, d, 2);
                if ((lane & 3) == 0) {
                    int lr = warpM * 32 + mi * 16 + rh * 8 + (lane >> 2);
                    redS[lr][warpN] = s;
                    redD[lr][warpN] = d;
                }
            }
        __syncthreads();
        if (tid < 128) {
            int rg = rowBase + tid;
            if (rg < M) {
                as_o[rg] = redS[tid][0] + redS[tid][1];
                ad_o[rg] = redD[tid][0] + redD[tid][1];
            }
        }
    }
}

// ================= layer-2 aggregation, two-phase; 2-edge unroll =================
__global__ __launch_bounds__(256) void agg2_kernel(
    const int* __restrict__ rowptr, const int* __restrict__ csrc,
    const float* __restrict__ as_v, const float* __restrict__ ad_v,
    const __half* __restrict__ x2h, float* __restrict__ p2,
    __half* __restrict__ y2h)
{
    int n = (blockIdx.x * 256 + threadIdx.x) >> 5;
    int lane = threadIdx.x & 31;
    if (n >= N_NODES) return;
    int start = rowptr[n], end = rowptr[n + 1];
    float adn = ad_v[n];

    // ---- phase 1: per-edge numerators ----
    float den = 0.f;
    for (int e = start + lane; e < end; e += 32) {
        int s = csrc[e];
        float l = as_v[s] + adn;
        l = fmaxf(l, 0.2f * l);
        float p = __expf(l);
        p2[e] = p;
        den += p;
    }
#pragma unroll
    for (int off = 16; off > 0; off >>= 1)
        den += __shfl_xor_sync(0xffffffff, den, off);
    __syncwarp();
    float inv = 1.f / den;

    // ---- phase 2: weighted gather-accumulate, 2-edge unroll ----
    float ax = 0.f, ay = 0.f, az = 0.f, aw = 0.f;
    const __half* xcol = x2h + lane * 4;
    int e = start;
    for (; e + 1 < end; e += 2) {
        int s0 = csrc[e], s1 = csrc[e + 1];
        float pa = p2[e], pb = p2[e + 1];
        uint2 q0 = *(const uint2*)(xcol + (size_t)s0 * C);
        uint2 q1 = *(const uint2*)(xcol + (size_t)s1 * C);
        float2 f00 = __half22float2(((const __half2*)&q0)[0]);
        float2 f01 = __half22float2(((const __half2*)&q0)[1]);
        float2 f10 = __half22float2(((const __half2*)&q1)[0]);
        float2 f11 = __half22float2(((const __half2*)&q1)[1]);
        ax += pa * f00.x + pb * f10.x;
        ay += pa * f00.y + pb * f10.y;
        az += pa * f01.x + pb * f11.x;
        aw += pa * f01.y + pb * f11.y;
    }
    if (e < end) {
        int s0 = csrc[e];
        float pa = p2[e];
        uint2 q0 = *(const uint2*)(xcol + (size_t)s0 * C);
        float2 f00 = __half22float2(((const __half2*)&q0)[0]);
        float2 f01 = __half22float2(((const __half2*)&q0)[1]);
        ax += pa * f00.x; ay += pa * f00.y; az += pa * f01.x; aw += pa * f01.y;
    }
    __half2 o0 = __floats2half2_rn(ax * inv, ay * inv);
    __half2 o1 = __floats2half2_rn(az * inv, aw * inv);
    uint2 o; o.x = *(unsigned int*)&o0; o.y = *(unsigned int*)&o1;
    *(uint2*)&y2h[(size_t)n * C + lane * 4] = o;
}

// ---------------- launch ----------------
extern "C" void kernel_launch(void* const* d_in, const int* in_sizes, int n_in,
                              void* d_out, int out_size)
{
    const float* x      = (const float*)d_in[0];
    const float* W1     = (const float*)d_in[1];
    const float* a_src1 = (const float*)d_in[2];
    const float* a_dst1 = (const float*)d_in[3];
    const float* b1     = (const float*)d_in[4];
    const float* W2     = (const float*)d_in[5];
    const float* a_src2 = (const float*)d_in[6];
    const float* a_dst2 = (const float*)d_in[7];
    const float* b2     = (const float*)d_in[8];
    const int*   ei     = (const int*)d_in[9];
    float* out = (float*)d_out;

    __half *xh, *W1s, *W2h, *yh, *x2h, *y2h;
    float *p1, *p2, *as1, *ad1, *as2, *ad2, *was1, *wad1, *was2, *wad2;
    int *rowptr, *cnt, *csrc, *rankp;
    cudaGetSymbolAddress((void**)&xh,     g_xh);
    cudaGetSymbolAddress((void**)&W1s,    g_W1s);
    cudaGetSymbolAddress((void**)&W2h,    g_W2h);
    cudaGetSymbolAddress((void**)&yh,     g_yh);
    cudaGetSymbolAddress((void**)&x2h,    g_x2h);
    cudaGetSymbolAddress((void**)&y2h,    g_y2h);
    cudaGetSymbolAddress((void**)&p1,     g_p1);
    cudaGetSymbolAddress((void**)&p2,     g_p2);
    cudaGetSymbolAddress((void**)&as1,    g_as1);
    cudaGetSymbolAddress((void**)&ad1,    g_ad1);
    cudaGetSymbolAddress((void**)&as2,    g_as2);
    cudaGetSymbolAddress((void**)&ad2,    g_ad2);
    cudaGetSymbolAddress((void**)&was1,   g_was1);
    cudaGetSymbolAddress((void**)&wad1,   g_wad1);
    cudaGetSymbolAddress((void**)&was2,   g_was2);
    cudaGetSymbolAddress((void**)&wad2,   g_wad2);
    cudaGetSymbolAddress((void**)&rankp,  g_rank);
    cudaGetSymbolAddress((void**)&rowptr, g_rowptr);
    cudaGetSymbolAddress((void**)&cnt,    g_cnt);
    cudaGetSymbolAddress((void**)&csrc,   g_csrc);

    const int TPB = 256;
    const int PREP_TOTAL = N_NODES * C / 4 + HC1 * C / 4 + C * C / 4;   // 660480
    int prep_blocks = (PREP_TOTAL + TPB - 1) / TPB;
    if (prep_blocks < (E_TOT + TPB - 1) / TPB) prep_blocks = (E_TOT + TPB - 1) / TPB;

    cudaFuncSetAttribute(scan_kernel, cudaFuncAttributeMaxDynamicSharedMemorySize,
                         SCAN_ELEMS * (int)sizeof(int));

    const int GEMM_GRID = (N_NODES + 127) / 128;   // 157
    const int WARP_GRID = (N_NODES * 32 + TPB - 1) / TPB;

    // 1) prep: wfold + converts + count/rank
    prep_kernel<<<prep_blocks, TPB>>>(x, W1, W2, a_src1, a_dst1, a_src2, a_dst2, ei,
                                      xh, W1s, W2h, was1, wad1, was2, wad2,
                                      cnt, rankp);
    // 2) scan
    scan_kernel<<<1, 1024, SCAN_ELEMS * sizeof(int)>>>(cnt, rowptr);
    // 3) fused: atomic-free scatter + alphas1
    fused_sa_kernel<<<SC_BLOCKS + AL_BLOCKS, TPB>>>(
        ei, rowptr, rankp, csrc, x, was1, wad1, as1, ad1);
    // 4) layer-1 aggregation (two-phase, 2-edge unroll) -> yh
    agg1_kernel<<<WARP_GRID, TPB>>>(rowptr, csrc, as1, ad1, xh, p1, yh);
    // 5) gemm-mid: x2 = ELU(yh * W1s + b1) fp16; epilogue computes layer-2 logits
    gemm_bias_elu_kernel<HC1, true, true><<<GEMM_GRID, TPB>>>(
        yh, W1s, b1, x2h, N_NODES, was2, wad2, as2, ad2);
    // 6) layer-2 aggregation (two-phase, 2-edge unroll) -> y2
    agg2_kernel<<<WARP_GRID, TPB>>>(rowptr, csrc, as2, ad2, x2h, p2, y2h);
    // 7) gemm-out: out = ELU(y2 * W2 + b2)
    gemm_bias_elu_kernel<C, false, false><<<GEMM_GRID, TPB>>>(
        y2h, W2h, b2, out, N_NODES, (const float*)nullptr, (const float*)nullptr,
        (float*)nullptr, (float*)nullptr);
}

// round 17
// speedup vs baseline: 1.2354x; 1.0248x over previous
#include <cuda_runtime.h>
#include <cuda_fp16.h>
#include <math.h>
#include <stdint.h>

#define N_NODES 20000
#define N_EDGES 640000
#define E_TOT   660000          // + self loops
#define H1      4
#define C       128
#define HC1     (H1 * C)        // 512

// ---------------- scratch (no allocations allowed) ----------------
__device__ __half g_xh[N_NODES * C];
__device__ __half g_W1s[HC1 * C];        // stacked+scaled: [512 x 128]
__device__ __half g_W2h[C * C];
__device__ __half g_yh[N_NODES * HC1];   // per-head aggregated x (normalized), fp16
__device__ __half g_x2h[N_NODES * C];
__device__ __half g_y2h[N_NODES * C];
__device__ float  g_p1[4 * E_TOT];       // layer-1 per-edge softmax numerators
__device__ float  g_p2[E_TOT];           // layer-2 per-edge numerators
__device__ float  g_as1[N_NODES * H1];
__device__ float  g_ad1[N_NODES * H1];
__device__ float  g_as2[N_NODES];
__device__ float  g_ad2[N_NODES];
__device__ float  g_was1[C * H1];
__device__ float  g_wad1[C * H1];
__device__ float  g_was2[C];
__device__ float  g_wad2[C];
__device__ int    g_rank[E_TOT];         // per-edge rank within its destination
__device__ int    g_rowptr[N_NODES + 1];
__device__ int    g_cnt[N_NODES];       // zero-initialized; scan re-zeroes after use
__device__ int    g_csrc[E_TOT];

__device__ __forceinline__ unsigned int smem_u32(const void* p)
{
    return (unsigned int)__cvta_generic_to_shared(p);
}
__device__ __forceinline__ unsigned long long pack_f32x2(float lo, float hi)
{
    unsigned long long r;
    asm("mov.b64 %0, {%1, %2};" : "=l"(r) : "f"(lo), "f"(hi));
    return r;
}
__device__ __forceinline__ void unpack_f32x2(float& lo, float& hi, unsigned long long v)
{
    asm("mov.b64 {%0, %1}, %2;" : "=f"(lo), "=f"(hi) : "l"(v));
}
__device__ __forceinline__ unsigned long long fma_f32x2(
    unsigned long long a, unsigned long long b, unsigned long long c)
{
    unsigned long long d;
    asm("fma.rn.f32x2 %0, %1, %2, %3;" : "=l"(d) : "l"(a), "l"(b), "l"(c));
    return d;
}

// ================= prep: wfold + fp16 converts (x, W1s stacked, W2) + degree count/rank =================
__global__ __launch_bounds__(256) void prep_kernel(
    const float* __restrict__ x,  const float* __restrict__ W1,
    const float* __restrict__ W2, const float* __restrict__ as1,
    const float* __restrict__ ad1, const float* __restrict__ as2,
    const float* __restrict__ ad2, const int* __restrict__ ei,
    __half* __restrict__ xh, __half* __restrict__ W1s, __half* __restrict__ W2h,
    float* __restrict__ w_as1, float* __restrict__ w_ad1,
    float* __restrict__ w_as2, float* __restrict__ w_ad2,
    int* __restrict__ cnt, int* __restrict__ rank)
{
    const int R0 = N_NODES * C / 4;      // 640000  x -> xh
    const int R1 = HC1 * C / 4;          // 16384   W1 -> W1s (transposed blocks, 0.25x)
    const int R2 = C * C / 4;            // 4096    W2 -> W2h
    int gid = blockIdx.x * blockDim.x + threadIdx.x;

    if (gid < R0) {
        float4 v = ((const float4*)x)[gid];
        __half2* d2 = (__half2*)(xh + (size_t)gid * 4);
        d2[0] = __floats2half2_rn(v.x, v.y);
        d2[1] = __floats2half2_rn(v.z, v.w);
    } else if (gid < R0 + R1) {
        int m = gid - R0;
        int r = m >> 5;                  // row of W1s: 0..511
        int jc = (m & 31) * 4;           // col
        int h = r >> 7, i = r & 127;
        float4 v = *(const float4*)&W1[(size_t)i * HC1 + h * C + jc];
        __half2* d2 = (__half2*)(W1s + (size_t)r * C + jc);
        d2[0] = __floats2half2_rn(0.25f * v.x, 0.25f * v.y);
        d2[1] = __floats2half2_rn(0.25f * v.z, 0.25f * v.w);
    } else if (gid < R0 + R1 + R2) {
        int m = gid - R0 - R1;
        float4 v = ((const float4*)W2)[m];
        __half2* d2 = (__half2*)(W2h + (size_t)m * 4);
        d2[0] = __floats2half2_rn(v.x, v.y);
        d2[1] = __floats2half2_rn(v.z, v.w);
    }
    if (gid < E_TOT) {
        int d = (gid < N_EDGES) ? ei[N_EDGES + gid] : (gid - N_EDGES);
        rank[gid] = atomicAdd(&cnt[d], 1);   // rank reused by atomic-free scatter
    }
    int w = gid >> 5, lane = gid & 31;
    if (w < 512) {
        int k = w >> 2, h = w & 3;
        float4 wv = *(const float4*)&W1[(size_t)k * HC1 + h * C + lane * 4];
        float4 av = *(const float4*)&as1[h * C + lane * 4];
        float4 dv = *(const float4*)&ad1[h * C + lane * 4];
        float ss = wv.x * av.x + wv.y * av.y + wv.z * av.z + wv.w * av.w;
        float sd = wv.x * dv.x + wv.y * dv.y + wv.z * dv.z + wv.w * dv.w;
#pragma unroll
        for (int off = 16; off > 0; off >>= 1) {
            ss += __shfl_down_sync(0xffffffff, ss, off);
            sd += __shfl_down_sync(0xffffffff, sd, off);
        }
        if (lane == 0) { w_as1[k * H1 + h] = ss; w_ad1[k * H1 + h] = sd; }
    } else if (w < 640) {
        int k = w - 512;
        float4 wv = *(const float4*)&W2[(size_t)k * C + lane * 4];
        float4 av = *(const float4*)&as2[lane * 4];
        float4 dv = *(const float4*)&ad2[lane * 4];
        float ss = wv.x * av.x + wv.y * av.y + wv.z * av.z + wv.w * av.w;
        float sd = wv.x * dv.x + wv.y * dv.y + wv.z * dv.z + wv.w * dv.w;
#pragma unroll
        for (int off = 16; off > 0; off >>= 1) {
            ss += __shfl_down_sync(0xffffffff, ss, off);
            sd += __shfl_down_sync(0xffffffff, sd, off);
        }
        if (lane == 0) { w_as2[k] = ss; w_ad2[k] = sd; }
    }
}

// ================= coalesced smem-staged scan (1 block); zeroes cnt afterward =================
#define SCAN_ELEMS 20480   // 1024 * 20
__global__ __launch_bounds__(1024) void scan_kernel(
    int* __restrict__ cnt, int* __restrict__ rowptr)
{
    extern __shared__ int sm[];
    __shared__ int part[1024];
    const int t = threadIdx.x;
    const int CHUNK = 20;

    for (int i = t; i < SCAN_ELEMS; i += 1024)
        sm[i] = (i < N_NODES) ? cnt[i] : 0;
    __syncthreads();

    int base = t * CHUNK;
    int s = 0;
#pragma unroll
    for (int k = 0; k < CHUNK; k++) s += sm[base + k];
    part[t] = s;
    __syncthreads();
    for (int off = 1; off < 1024; off <<= 1) {
        int v = (t >= off) ? part[t - off] : 0;
        __syncthreads();
        part[t] += v;
        __syncthreads();
    }
    int run = part[t] - s;
#pragma unroll
    for (int k = 0; k < CHUNK; k++) {
        int c = sm[base + k];
        sm[base + k] = run;
        run += c;
    }
    __syncthreads();
    for (int i = t; i < N_NODES; i += 1024) {
        rowptr[i] = sm[i];
        cnt[i] = 0;
    }
    if (t == 1023) rowptr[N_NODES] = part[1023];
}

// ================= fused: atomic-free CSR scatter + layer-1 logits =================
#define SC_BLOCKS  ((E_TOT + 255) / 256)
#define AL_BLOCKS  ((N_NODES * 32 + 255) / 256)
__global__ __launch_bounds__(256) void fused_sa_kernel(
    const int* __restrict__ ei, const int* __restrict__ rowptr,
    const int* __restrict__ rank, int* __restrict__ csrc,
    const float* __restrict__ x, const float* __restrict__ w_as1,
    const float* __restrict__ w_ad1, float* __restrict__ as_o,
    float* __restrict__ ad_o)
{
    int bid = blockIdx.x;
    if (bid < SC_BLOCKS) {
        int i = bid * 256 + threadIdx.x;
        if (i < E_TOT) {
            int s, d;
            if (i < N_EDGES) { s = ei[i]; d = ei[N_EDGES + i]; }
            else { s = d = i - N_EDGES; }
            csrc[rowptr[d] + rank[i]] = s;   // no atomics: rank precomputed in prep
        }
        return;
    }
    bid -= SC_BLOCKS;
    {
        __shared__ float sw_s[C * H1], sw_d[C * H1];
        for (int i = threadIdx.x; i < C * H1; i += 256) {
            sw_s[i] = w_as1[i]; sw_d[i] = w_ad1[i];
        }
        __syncthreads();
        int n = (bid * 256 + threadIdx.x) >> 5;
        int lane = threadIdx.x & 31;
        if (n >= N_NODES) return;
        float4 xv = *(const float4*)&x[(size_t)n * C + lane * 4];
        float xs[4] = {xv.x, xv.y, xv.z, xv.w};
        float ps[4] = {0, 0, 0, 0}, pd[4] = {0, 0, 0, 0};
#pragma unroll
        for (int j = 0; j < 4; j++) {
            int k = lane * 4 + j;
#pragma unroll
            for (int h = 0; h < 4; h++) {
                ps[h] += xs[j] * sw_s[k * 4 + h];
                pd[h] += xs[j] * sw_d[k * 4 + h];
            }
        }
#pragma unroll
        for (int off = 16; off > 0; off >>= 1) {
#pragma unroll
            for (int h = 0; h < 4; h++) {
                ps[h] += __shfl_down_sync(0xffffffff, ps[h], off);
                pd[h] += __shfl_down_sync(0xffffffff, pd[h], off);
            }
        }
        if (lane == 0) {
            *(float4*)&as_o[n * 4] = make_float4(ps[0], ps[1], ps[2], ps[3]);
            *(float4*)&ad_o[n * 4] = make_float4(pd[0], pd[1], pd[2], pd[3]);
        }
    }
}

// ================= layer-1 aggregation, two-phase; lane = 4ch x 4 heads; FFMA2; 2-edge unroll =================
__global__ __launch_bounds__(256) void agg1_kernel(
    const int* __restrict__ rowptr, const int* __restrict__ csrc,
    const float* __restrict__ as_v, const float* __restrict__ ad_v,
    const __half* __restrict__ xh, float* __restrict__ p1,
    __half* __restrict__ yh)
{
    int n = (blockIdx.x * 256 + threadIdx.x) >> 5;
    int lane = threadIdx.x & 31;
    if (n >= N_NODES) return;
    int start = rowptr[n], end = rowptr[n + 1];
    float4 adn = *(const float4*)&ad_v[n * 4];

    // ---- phase 1: per-edge softmax numerators (lanes parallel over edges) ----
    float d0 = 0.f, d1 = 0.f, d2 = 0.f, d3 = 0.f;
    for (int e = start + lane; e < end; e += 32) {
        int s = csrc[e];
        float4 lg = *(const float4*)&as_v[s * 4];
        float l0 = lg.x + adn.x; l0 = fmaxf(l0, 0.2f * l0);
        float l1 = lg.y + adn.y; l1 = fmaxf(l1, 0.2f * l1);
        float l2 = lg.z + adn.z; l2 = fmaxf(l2, 0.2f * l2);
        float l3 = lg.w + adn.w; l3 = fmaxf(l3, 0.2f * l3);
        float p0 = __expf(l0), pp1 = __expf(l1), p2 = __expf(l2), p3 = __expf(l3);
        *(float4*)&p1[(size_t)e * 4] = make_float4(p0, pp1, p2, p3);
        d0 += p0; d1 += pp1; d2 += p2; d3 += p3;
    }
#pragma unroll
    for (int off = 16; off > 0; off >>= 1) {
        d0 += __shfl_xor_sync(0xffffffff, d0, off);
        d1 += __shfl_xor_sync(0xffffffff, d1, off);
        d2 += __shfl_xor_sync(0xffffffff, d2, off);
        d3 += __shfl_xor_sync(0xffffffff, d3, off);
    }
    __syncwarp();                         // order p1 stores before phase-2 loads

    // ---- phase 2: lane owns channels [lane*4, lane*4+4), all 4 heads; FFMA2; 2-edge unroll ----
    unsigned long long acc2[4][2];
#pragma unroll
    for (int h = 0; h < 4; h++) { acc2[h][0] = 0ull; acc2[h][1] = 0ull; }

    const __half* xcol = xh + lane * 4;
    int e = start;
    for (; e + 1 < end; e += 2) {
        int s0 = csrc[e], s1 = csrc[e + 1];
        float4 pa = *(const float4*)&p1[(size_t)e * 4];
        float4 pb = *(const float4*)&p1[(size_t)(e + 1) * 4];
        uint2 q0 = *(const uint2*)(xcol + (size_t)s0 * C);
        uint2 q1 = *(const uint2*)(xcol + (size_t)s1 * C);
        float2 f00 = __half22float2(((const __half2*)&q0)[0]);
        float2 f01 = __half22float2(((const __half2*)&q0)[1]);
        float2 f10 = __half22float2(((const __half2*)&q1)[0]);
        float2 f11 = __half22float2(((const __half2*)&q1)[1]);
        unsigned long long fa0 = pack_f32x2(f00.x, f00.y);
        unsigned long long fa1 = pack_f32x2(f01.x, f01.y);
        unsigned long long fb0 = pack_f32x2(f10.x, f10.y);
        unsigned long long fb1 = pack_f32x2(f11.x, f11.y);
        float pav[4] = {pa.x, pa.y, pa.z, pa.w};
        float pbv[4] = {pb.x, pb.y, pb.z, pb.w};
#pragma unroll
        for (int h = 0; h < 4; h++) {
            unsigned long long ph = pack_f32x2(pav[h], pav[h]);
            unsigned long long qh = pack_f32x2(pbv[h], pbv[h]);
            acc2[h][0] = fma_f32x2(fa0, ph, acc2[h][0]);
            acc2[h][1] = fma_f32x2(fa1, ph, acc2[h][1]);
            acc2[h][0] = fma_f32x2(fb0, qh, acc2[h][0]);
            acc2[h][1] = fma_f32x2(fb1, qh, acc2[h][1]);
        }
    }
    if (e < end) {
        int s0 = csrc[e];
        float4 pa = *(const float4*)&p1[(size_t)e * 4];
        uint2 q0 = *(const uint2*)(xcol + (size_t)s0 * C);
        float2 f00 = __half22float2(((const __half2*)&q0)[0]);
        float2 f01 = __half22float2(((const __half2*)&q0)[1]);
        unsigned long long fa0 = pack_f32x2(f00.x, f00.y);
        unsigned long long fa1 = pack_f32x2(f01.x, f01.y);
        float pav[4] = {pa.x, pa.y, pa.z, pa.w};
#pragma unroll
        for (int h = 0; h < 4; h++) {
            unsigned long long ph = pack_f32x2(pav[h], pav[h]);
            acc2[h][0] = fma_f32x2(fa0, ph, acc2[h][0]);
            acc2[h][1] = fma_f32x2(fa1, ph, acc2[h][1]);
        }
    }

    float invs[4] = {1.f / d0, 1.f / d1, 1.f / d2, 1.f / d3};
#pragma unroll
    for (int h = 0; h < 4; h++) {
        float a0, a1, a2, a3;
        unpack_f32x2(a0, a1, acc2[h][0]);
        unpack_f32x2(a2, a3, acc2[h][1]);
        __half hv[4];
        hv[0] = __float2half(a0 * invs[h]);
        hv[1] = __float2half(a1 * invs[h]);
        hv[2] = __float2half(a2 * invs[h]);
        hv[3] = __float2half(a3 * invs[h]);
        *(uint2*)&yh[(size_t)n * HC1 + h * C + lane * 4] = *(uint2*)hv;
    }
}

// ================= tensor-core GEMM + bias + ELU (+ optional layer-2 logits) =================
// C[M,128] = A[M,KDIM] * B[KDIM,128]; CTA 128x128, BK=64, 8 warps (4M x 2N)
template <int KDIM, bool OUT_HALF, bool DO_LOGITS>
__global__ __launch_bounds__(256) void gemm_bias_elu_kernel(
    const __half* __restrict__ A, const __half* __restrict__ B,
    const float* __restrict__ bias, void* __restrict__ Cout, int M,
    const float* __restrict__ w_s, const float* __restrict__ w_d,
    float* __restrict__ as_o, float* __restrict__ ad_o)
{
    __shared__ __half As[128][64];
    __shared__ __half Bs[64][128];
    __shared__ float sw_s[DO_LOGITS ? C : 1], sw_d[DO_LOGITS ? C : 1];
    __shared__ float redS[DO_LOGITS ? 128 : 1][2], redD[DO_LOGITS ? 128 : 1][2];

    const int tid = threadIdx.x;
    const int lane = tid & 31, wid = tid >> 5;
    const int warpM = wid >> 1, warpN = wid & 1;
    const int rowBase = blockIdx.x * 128;

    if (DO_LOGITS) {
        for (int i = tid; i < C; i += 256) { sw_s[i] = w_s[i]; sw_d[i] = w_d[i]; }
    }

    float acc[2][8][4];
#pragma unroll
    for (int mi = 0; mi < 2; mi++)
#pragma unroll
        for (int ni = 0; ni < 8; ni++)
#pragma unroll
            for (int q = 0; q < 4; q++) acc[mi][ni][q] = 0.f;

    const int arow0 = warpM * 32 + (lane & 15);
    const int brow0 = (lane & 15);
    const int hi = (lane >> 4);

    for (int kt = 0; kt < KDIM / 64; kt++) {
#pragma unroll
        for (int i = tid; i < 1024; i += 256) {
            int r = i >> 3, ch = i & 7;
            int gr = rowBase + r;
            uint4 v = make_uint4(0u, 0u, 0u, 0u);
            if (gr < M) v = *(const uint4*)&A[(size_t)gr * KDIM + kt * 64 + ch * 8];
            int sch = ch ^ (r & 7);
            *(uint4*)&As[r][sch * 8] = v;
        }
#pragma unroll
        for (int i = tid; i < 1024; i += 256) {
            int r = i >> 4, ch = i & 15;
            uint4 v = *(const uint4*)&B[(size_t)(kt * 64 + r) * C + ch * 8];
            int sch = (ch & 8) | ((ch & 7) ^ (r & 7));
            *(uint4*)&Bs[r][sch * 8] = v;
        }
        __syncthreads();

#pragma unroll
        for (int kk = 0; kk < 4; kk++) {
            unsigned int a[2][4];
#pragma unroll
            for (int mi = 0; mi < 2; mi++) {
                int r = arow0 + mi * 16;
                int ch = (kk * 2 + hi) ^ (r & 7);
                unsigned int addr = smem_u32(&As[r][ch * 8]);
                asm volatile("ldmatrix.sync.aligned.m8n8.x4.shared.b16 {%0,%1,%2,%3}, [%4];"
                    : "=r"(a[mi][0]), "=r"(a[mi][1]), "=r"(a[mi][2]), "=r"(a[mi][3])
                    : "r"(addr));
            }
            unsigned int b[8][2];
#pragma unroll
            for (int np = 0; np < 4; np++) {
                int r = kk * 16 + brow0;
                int chL = warpN * 8 + np * 2 + hi;
                int ch = (chL & 8) | ((chL & 7) ^ (r & 7));
                unsigned int addr = smem_u32(&Bs[r][ch * 8]);
                unsigned int r0, r1, r2, r3;
                asm volatile("ldmatrix.sync.aligned.m8n8.x4.trans.shared.b16 {%0,%1,%2,%3}, [%4];"
                    : "=r"(r0), "=r"(r1), "=r"(r2), "=r"(r3) : "r"(addr));
                b[np * 2][0] = r0;     b[np * 2][1] = r1;
                b[np * 2 + 1][0] = r2; b[np * 2 + 1][1] = r3;
            }
#pragma unroll
            for (int mi = 0; mi < 2; mi++)
#pragma unroll
                for (int ni = 0; ni < 8; ni++)
                    asm volatile(
                        "mma.sync.aligned.m16n8k16.row.col.f32.f16.f16.f32 "
                        "{%0,%1,%2,%3},{%4,%5,%6,%7},{%8,%9},{%0,%1,%2,%3};"
                        : "+f"(acc[mi][ni][0]), "+f"(acc[mi][ni][1]),
                          "+f"(acc[mi][ni][2]), "+f"(acc[mi][ni][3])
                        : "r"(a[mi][0]), "r"(a[mi][1]), "r"(a[mi][2]), "r"(a[mi][3]),
                          "r"(b[ni][0]), "r"(b[ni][1]));
        }
        __syncthreads();
    }

    // ---- epilogue: bias + ELU (+ logits) ----
    float psum[2][2], pdum[2][2];
    if (DO_LOGITS) {
        psum[0][0] = psum[0][1] = psum[1][0] = psum[1][1] = 0.f;
        pdum[0][0] = pdum[0][1] = pdum[1][0] = pdum[1][1] = 0.f;
    }
#pragma unroll
    for (int mi = 0; mi < 2; mi++) {
        int r0 = rowBase + warpM * 32 + mi * 16 + (lane >> 2);
#pragma unroll
        for (int ni = 0; ni < 8; ni++) {
            int col = warpN * 64 + ni * 8 + (lane & 3) * 2;
            float b0 = bias[col], b1v = bias[col + 1];
            float v0 = acc[mi][ni][0] + b0;  v0 = v0 > 0.f ? v0 : expm1f(v0);
            float v1 = acc[mi][ni][1] + b1v; v1 = v1 > 0.f ? v1 : expm1f(v1);
            float v2 = acc[mi][ni][2] + b0;  v2 = v2 > 0.f ? v2 : expm1f(v2);
            float v3 = acc[mi][ni][3] + b1v; v3 = v3 > 0.f ? v3 : expm1f(v3);
            if (DO_LOGITS) {
                psum[mi][0] += v0 * sw_s[col] + v1 * sw_s[col + 1];
                psum[mi][1] += v2 * sw_s[col] + v3 * sw_s[col + 1];
                pdum[mi][0] += v0 * sw_d[col] + v1 * sw_d[col + 1];
                pdum[mi][1] += v2 * sw_d[col] + v3 * sw_d[col + 1];
            }
            if (OUT_HALF) {
                __half* Ch = (__half*)Cout;
                if (r0 < M)
                    *(__half2*)&Ch[(size_t)r0 * C + col] = __floats2half2_rn(v0, v1);
                if (r0 + 8 < M)
                    *(__half2*)&Ch[(size_t)(r0 + 8) * C + col] = __floats2half2_rn(v2, v3);
            } else {
                float* Cf = (float*)Cout;
                if (r0 < M)
                    *(float2*)&Cf[(size_t)r0 * C + col] = make_float2(v0, v1);
                if (r0 + 8 < M)
                    *(float2*)&Cf[(size_t)(r0 + 8) * C + col] = make_float2(v2, v3);
            }
        }
    }
    if (DO_LOGITS) {
#pragma unroll
        for (int mi = 0; mi < 2; mi++)
#pragma unroll
            for (int rh = 0; rh < 2; rh++) {
                float s = psum[mi][rh], d = pdum[mi][rh];
                s += __shfl_xor_sync(0xffffffff, s, 1);
                s += __shfl_xor_sync(0xffffffff, s, 2);
                d += __shfl_xor_sync(0xffffffff, d, 1);
                d += __shfl_xor_sync(0xffffffff, d, 2);
                if ((lane & 3) == 0) {
                    int lr = warpM * 32 + mi * 16 + rh * 8 + (lane >> 2);
                    redS[lr][warpN] = s;
                    redD[lr][warpN] = d;
                }
            }
        __syncthreads();
        if (tid < 128) {
            int rg = rowBase + tid;
            if (rg < M) {
                as_o[rg] = redS[tid][0] + redS[tid][1];
                ad_o[rg] = redD[tid][0] + redD[tid][1];
            }
        }
    }
}

// ================= layer-2 aggregation, two-phase; FFMA2; 2-edge unroll =================
__global__ __launch_bounds__(256) void agg2_kernel(
    const int* __restrict__ rowptr, const int* __restrict__ csrc,
    const float* __restrict__ as_v, const float* __restrict__ ad_v,
    const __half* __restrict__ x2h, float* __restrict__ p2,
    __half* __restrict__ y2h)
{
    int n = (blockIdx.x * 256 + threadIdx.x) >> 5;
    int lane = threadIdx.x & 31;
    if (n >= N_NODES) return;
    int start = rowptr[n], end = rowptr[n + 1];
    float adn = ad_v[n];

    // ---- phase 1: per-edge numerators ----
    float den = 0.f;
    for (int e = start + lane; e < end; e += 32) {
        int s = csrc[e];
        float l = as_v[s] + adn;
        l = fmaxf(l, 0.2f * l);
        float p = __expf(l);
        p2[e] = p;
        den += p;
    }
#pragma unroll
    for (int off = 16; off > 0; off >>= 1)
        den += __shfl_xor_sync(0xffffffff, den, off);
    __syncwarp();
    float inv = 1.f / den;

    // ---- phase 2: weighted gather-accumulate, FFMA2, 2-edge unroll ----
    unsigned long long a0 = 0ull, a1 = 0ull;
    const __half* xcol = x2h + lane * 4;
    int e = start;
    for (; e + 1 < end; e += 2) {
        int s0 = csrc[e], s1 = csrc[e + 1];
        float pa = p2[e], pb = p2[e + 1];
        uint2 q0 = *(const uint2*)(xcol + (size_t)s0 * C);
        uint2 q1 = *(const uint2*)(xcol + (size_t)s1 * C);
        float2 f00 = __half22float2(((const __half2*)&q0)[0]);
        float2 f01 = __half22float2(((const __half2*)&q0)[1]);
        float2 f10 = __half22float2(((const __half2*)&q1)[0]);
        float2 f11 = __half22float2(((const __half2*)&q1)[1]);
        unsigned long long ph = pack_f32x2(pa, pa);
        unsigned long long qh = pack_f32x2(pb, pb);
        a0 = fma_f32x2(pack_f32x2(f00.x, f00.y), ph, a0);
        a1 = fma_f32x2(pack_f32x2(f01.x, f01.y), ph, a1);
        a0 = fma_f32x2(pack_f32x2(f10.x, f10.y), qh, a0);
        a1 = fma_f32x2(pack_f32x2(f11.x, f11.y), qh, a1);
    }
    if (e < end) {
        int s0 = csrc[e];
        float pa = p2[e];
        uint2 q0 = *(const uint2*)(xcol + (size_t)s0 * C);
        float2 f00 = __half22float2(((const __half2*)&q0)[0]);
        float2 f01 = __half22float2(((const __half2*)&q0)[1]);
        unsigned long long ph = pack_f32x2(pa, pa);
        a0 = fma_f32x2(pack_f32x2(f00.x, f00.y), ph, a0);
        a1 = fma_f32x2(pack_f32x2(f01.x, f01.y), ph, a1);
    }
    float ax, ay, az, aw;
    unpack_f32x2(ax, ay, a0);
    unpack_f32x2(az, aw, a1);
    __half2 o0 = __floats2half2_rn(ax * inv, ay * inv);
    __half2 o1 = __floats2half2_rn(az * inv, aw * inv);
    uint2 o; o.x = *(unsigned int*)&o0; o.y = *(unsigned int*)&o1;
    *(uint2*)&y2h[(size_t)n * C + lane * 4] = o;
}

// ---------------- launch ----------------
extern "C" void kernel_launch(void* const* d_in, const int* in_sizes, int n_in,
                              void* d_out, int out_size)
{
    const float* x      = (const float*)d_in[0];
    const float* W1     = (const float*)d_in[1];
    const float* a_src1 = (const float*)d_in[2];
    const float* a_dst1 = (const float*)d_in[3];
    const float* b1     = (const float*)d_in[4];
    const float* W2     = (const float*)d_in[5];
    const float* a_src2 = (const float*)d_in[6];
    const float* a_dst2 = (const float*)d_in[7];
    const float* b2     = (const float*)d_in[8];
    const int*   ei     = (const int*)d_in[9];
    float* out = (float*)d_out;

    __half *xh, *W1s, *W2h, *yh, *x2h, *y2h;
    float *p1, *p2, *as1, *ad1, *as2, *ad2, *was1, *wad1, *was2, *wad2;
    int *rowptr, *cnt, *csrc, *rankp;
    cudaGetSymbolAddress((void**)&xh,     g_xh);
    cudaGetSymbolAddress((void**)&W1s,    g_W1s);
    cudaGetSymbolAddress((void**)&W2h,    g_W2h);
    cudaGetSymbolAddress((void**)&yh,     g_yh);
    cudaGetSymbolAddress((void**)&x2h,    g_x2h);
    cudaGetSymbolAddress((void**)&y2h,    g_y2h);
    cudaGetSymbolAddress((void**)&p1,     g_p1);
    cudaGetSymbolAddress((void**)&p2,     g_p2);
    cudaGetSymbolAddress((void**)&as1,    g_as1);
    cudaGetSymbolAddress((void**)&ad1,    g_ad1);
    cudaGetSymbolAddress((void**)&as2,    g_as2);
    cudaGetSymbolAddress((void**)&ad2,    g_ad2);
    cudaGetSymbolAddress((void**)&was1,   g_was1);
    cudaGetSymbolAddress((void**)&wad1,   g_wad1);
    cudaGetSymbolAddress((void**)&was2,   g_was2);
    cudaGetSymbolAddress((void**)&wad2,   g_wad2);
    cudaGetSymbolAddress((void**)&rankp,  g_rank);
    cudaGetSymbolAddress((void**)&rowptr, g_rowptr);
    cudaGetSymbolAddress((void**)&cnt,    g_cnt);
    cudaGetSymbolAddress((void**)&csrc,   g_csrc);

    const int TPB = 256;
    const int PREP_TOTAL = N_NODES * C / 4 + HC1 * C / 4 + C * C / 4;   // 660480
    int prep_blocks = (PREP_TOTAL + TPB - 1) / TPB;
    if (prep_blocks < (E_TOT + TPB - 1) / TPB) prep_blocks = (E_TOT + TPB - 1) / TPB;

    cudaFuncSetAttribute(scan_kernel, cudaFuncAttributeMaxDynamicSharedMemorySize,
                         SCAN_ELEMS * (int)sizeof(int));

    const int GEMM_GRID = (N_NODES + 127) / 128;   // 157
    const int WARP_GRID = (N_NODES * 32 + TPB - 1) / TPB;

    // 1) prep: wfold + converts + count/rank
    prep_kernel<<<prep_blocks, TPB>>>(x, W1, W2, a_src1, a_dst1, a_src2, a_dst2, ei,
                                      xh, W1s, W2h, was1, wad1, was2, wad2,
                                      cnt, rankp);
    // 2) scan
    scan_kernel<<<1, 1024, SCAN_ELEMS * sizeof(int)>>>(cnt, rowptr);
    // 3) fused: atomic-free scatter + alphas1
    fused_sa_kernel<<<SC_BLOCKS + AL_BLOCKS, TPB>>>(
        ei, rowptr, rankp, csrc, x, was1, wad1, as1, ad1);
    // 4) layer-1 aggregation (two-phase, FFMA2, 2-edge unroll) -> yh
    agg1_kernel<<<WARP_GRID, TPB>>>(rowptr, csrc, as1, ad1, xh, p1, yh);
    // 5) gemm-mid: x2 = ELU(yh * W1s + b1) fp16; epilogue computes layer-2 logits
    gemm_bias_elu_kernel<HC1, true, true><<<GEMM_GRID, TPB>>>(
        yh, W1s, b1, x2h, N_NODES, was2, wad2, as2, ad2);
    // 6) layer-2 aggregation (two-phase, FFMA2, 2-edge unroll) -> y2
    agg2_kernel<<<WARP_GRID, TPB>>>(rowptr, csrc, as2, ad2, x2h, p2, y2h);
    // 7) gemm-out: out = ELU(y2 * W2 + b2)
    gemm_bias_elu_kernel<C, false, false><<<GEMM_GRID, TPB>>>(
        y2h, W2h, b2, out, N_NODES, (const float*)nullptr, (const float*)nullptr,
        (float*)nullptr, (float*)nullptr);
}